// round 13
// baseline (speedup 1.0000x reference)
#include <cuda_runtime.h>
#include <cstdint>

// ---------------- problem constants ----------------
#define BATCH   4096
#define FRAME   267
#define LATENT  32
#define HIDDEN  256
#define GATE_H  64
#define EXPERTS 6
#define IN0     (LATENT + FRAME)    // 299
#define IN1     (LATENT + HIDDEN)   // 288
#define OUTD    FRAME               // 267

#define OFF_MU  (BATCH * OUTD)
#define OFF_LV  (OFF_MU + BATCH * LATENT)

// ---------------- scratch (allocation-free) ----------------
__device__ float g_h1[BATCH * HIDDEN];
__device__ float g_h2[BATCH * HIDDEN];
__device__ float g_coef[BATCH * EXPERTS];
// packed decoder inputs (16B-aligned rows)
__device__ __align__(16) float g_q0[BATCH * 320];   // [z | c | 0pad]
__device__ __align__(16) float g_q1[BATCH * 288];   // [z | d1]
__device__ __align__(16) float g_q2[BATCH * 288];   // [z | d2]

__device__ __forceinline__ float elu1(float x) { return x > 0.f ? x : expm1f(x); }

__device__ __forceinline__ float tf32r(float x) {
    float y;
    asm("cvt.rna.tf32.f32 %0, %1;" : "=f"(y) : "f"(x));
    return y;
}

#define BK 32

// Permuted smem layout: element k of a row lives at column
//   p(k) = (k&3)*8 + (k>>2)            (k in [0,32))
// so the 8 values thread tg needs for all 4 k-steps (k = tg+4j)
// sit contiguously at [tg*8, tg*8+8) -> two conflict-free LDS.128.
// Row stride 36 makes bank = 4*gid + 8*tg: each 8-lane phase hits
// all 32 banks exactly once.

// consumer fragment loader (shared by all kernels)
#define LOAD_FRAGS(AsBuf, BsBuf)                                            \
    float al[8], ah[8], bf[4][8];                                           \
    {                                                                       \
        const float4* p0 = reinterpret_cast<const float4*>(&AsBuf[wm16 + gid][0]);     \
        const float4* p1 = reinterpret_cast<const float4*>(&AsBuf[wm16 + gid + 8][0]); \
        float4 u0 = p0[tg * 2], u1 = p0[tg * 2 + 1];                        \
        float4 v0 = p1[tg * 2], v1 = p1[tg * 2 + 1];                        \
        al[0]=u0.x; al[1]=u0.y; al[2]=u0.z; al[3]=u0.w;                     \
        al[4]=u1.x; al[5]=u1.y; al[6]=u1.z; al[7]=u1.w;                     \
        ah[0]=v0.x; ah[1]=v0.y; ah[2]=v0.z; ah[3]=v0.w;                     \
        ah[4]=v1.x; ah[5]=v1.y; ah[6]=v1.z; ah[7]=v1.w;                     \
    }                                                                       \
    _Pragma("unroll")                                                       \
    for (int t4 = 0; t4 < 4; t4++) {                                        \
        const float4* cp = reinterpret_cast<const float4*>(&BsBuf[wn32 + (t4 << 3) + gid][0]); \
        float4 w0 = cp[tg * 2], w1 = cp[tg * 2 + 1];                        \
        bf[t4][0]=w0.x; bf[t4][1]=w0.y; bf[t4][2]=w0.z; bf[t4][3]=w0.w;     \
        bf[t4][4]=w1.x; bf[t4][5]=w1.y; bf[t4][6]=w1.z; bf[t4][7]=w1.w;     \
    }

#define MMA_TILE(accv)                                                      \
    _Pragma("unroll")                                                       \
    for (int ks = 0; ks < 4; ks++) {                                        \
        const int j0 = 2 * ks, j1 = 2 * ks + 1;                             \
        uint32_t a0 = __float_as_uint(al[j0]);                              \
        uint32_t a1 = __float_as_uint(ah[j0]);                              \
        uint32_t a2 = __float_as_uint(al[j1]);                              \
        uint32_t a3 = __float_as_uint(ah[j1]);                              \
        _Pragma("unroll")                                                   \
        for (int t4 = 0; t4 < 4; t4++) {                                    \
            uint32_t b0 = __float_as_uint(bf[t4][j0]);                      \
            uint32_t b1 = __float_as_uint(bf[t4][j1]);                      \
            asm volatile(                                                   \
                "mma.sync.aligned.m16n8k8.row.col.f32.tf32.tf32.f32 "       \
                "{%0,%1,%2,%3}, {%4,%5,%6,%7}, {%8,%9}, {%0,%1,%2,%3};\n"   \
                : "+f"(accv[t4][0]), "+f"(accv[t4][1]),                     \
                  "+f"(accv[t4][2]), "+f"(accv[t4][3])                      \
                : "r"(a0), "r"(a1), "r"(a2), "r"(a3), "r"(b0), "r"(b1));    \
        }                                                                   \
    }

// ============================================================
// Encoder/gate GEMM — double-buffered, permuted fragment layout.
// Tile 64x64x32, 256 threads, 8 warps (4m x 2n), warp tile m16n32.
// ============================================================
template<int N_, int K0_, int DIN_, int ACT_>
__global__ __launch_bounds__(256) void enc_gemm(
    const float* __restrict__ A0, int lda0,
    const float* __restrict__ A1, int lda1,
    const float* __restrict__ W, const float* __restrict__ bias,
    float* __restrict__ C, int ldc)
{
    constexpr int Ktot = DIN_;
    constexpr int NT   = (Ktot + BK - 1) / BK;
    __shared__ __align__(16) float As[2][64][36];
    __shared__ __align__(16) float Bs[2][64][36];   // n-major permuted

    const int tid  = threadIdx.x;
    const int lane = tid & 31;
    const int wid  = tid >> 5;
    const int wm16 = (wid >> 1) << 4;
    const int wn32 = (wid & 1) << 5;
    const int gid  = lane >> 2;
    const int tg   = lane & 3;

    const int bm_ = blockIdx.y * 64;
    const int bn_ = blockIdx.x * 64;

    const int amL = tid >> 3;
    const int akq = (tid & 7) << 2;
    const int aj  = tid & 7;
    const int bkL = tid >> 4;
    const int bnb = (tid & 15) << 2;

    float avv[2][4], bvv[2][4];

    auto ldgA = [&](int t) {
        const int kt = t * BK;
        #pragma unroll
        for (int half = 0; half < 2; half++) {
            const int m = bm_ + amL + half * 32;
            #pragma unroll
            for (int j = 0; j < 4; j++) {
                const int ig = kt + akq + j;
                float val = 0.f;
                if ((Ktot % BK == 0) || ig < Ktot)
                    val = (ig < K0_) ? __ldg(&A0[m * lda0 + ig])
                                     : __ldg(&A1[m * lda1 + (ig - K0_)]);
                avv[half][j] = val;
            }
        }
    };
    auto ldgB = [&](int t) {
        const int kt = t * BK;
        #pragma unroll
        for (int half = 0; half < 2; half++) {
            const int kg = kt + bkL + half * 16;
            const bool kok = (Ktot % BK == 0) || (kg < Ktot);
            #pragma unroll
            for (int j = 0; j < 4; j++) {
                const int n = bn_ + bnb + j;
                float val = 0.f;
                if (kok && ((N_ % 64) == 0 || n < N_))
                    val = __ldg(&W[(size_t)kg * N_ + n]);
                bvv[half][j] = val;
            }
        }
    };
    auto sts = [&](int buf) {
        #pragma unroll
        for (int half = 0; half < 2; half++) {
            const int mL = amL + half * 32;
            #pragma unroll
            for (int j = 0; j < 4; j++)
                As[buf][mL][j * 8 + aj] = tf32r(avv[half][j]);
        }
        #pragma unroll
        for (int half = 0; half < 2; half++) {
            const int kL = bkL + half * 16;
            const int pB = (kL & 3) * 8 + (kL >> 2);
            #pragma unroll
            for (int j = 0; j < 4; j++)
                Bs[buf][bnb + j][pB] = tf32r(bvv[half][j]);
        }
    };

    float acc[4][4] = {};

    ldgA(0); ldgB(0);
    sts(0);
    __syncthreads();

    for (int t = 0; t < NT; t++) {
        const int cur = t & 1;
        const bool more = (t + 1 < NT);
        if (more) { ldgA(t + 1); ldgB(t + 1); }

        LOAD_FRAGS(As[cur], Bs[cur])
        MMA_TILE(acc)

        if (more) sts(1 - cur);
        __syncthreads();
    }

    const int r0 = bm_ + wm16 + gid;
    const int r1 = r0 + 8;
    #pragma unroll
    for (int t = 0; t < 4; t++) {
        #pragma unroll
        for (int q = 0; q < 4; q++) {
            const int r  = (q < 2) ? r0 : r1;
            const int colL = wn32 + (t << 3) + (tg << 1) + (q & 1);
            const int cG = bn_ + colL;
            if ((N_ % 64) == 0 || cG < N_) {
                float v = acc[t][q] + __ldg(&bias[cG]);
                if (ACT_ == 1) v = elu1(v);
                C[r * ldc + cG] = v;
            }
        }
    }
}

// ============================================================
// mid2: dual GEMM (mu|lv, K=523) + z + gate0 GEMM (K=299) + gate1
// + gate2 + softmax — one launch, 64 rows/block, grid (1,64).
// Permuted fragment layout in phases A/B. z passes A->B via zsm.
// ============================================================
__global__ __launch_bounds__(256) void mid2(
    const float* __restrict__ x,   const float* __restrict__ h2,
    const float* __restrict__ wmu, const float* __restrict__ bmu,
    const float* __restrict__ wlv, const float* __restrict__ blv,
    const float* __restrict__ epsv, const float* __restrict__ cc,
    const float* __restrict__ gw0, const float* __restrict__ gb0,
    const float* __restrict__ gw1, const float* __restrict__ gb1,
    const float* __restrict__ gw2, const float* __restrict__ gb2,
    float* __restrict__ mu_out, float* __restrict__ lv_out,
    float* __restrict__ q0, float* __restrict__ q1, float* __restrict__ q2,
    float* __restrict__ coeff)
{
    __shared__ __align__(16) float As[2][64][36];   // overlays: muS, g2s
    __shared__ __align__(16) float Bs[2][64][36];   // overlays: lvS, w1s
    __shared__ float g1s[64][65];
    __shared__ float zsm[64][33];

    const int tid  = threadIdx.x;
    const int lane = tid & 31;
    const int wid  = tid >> 5;
    const int wm16 = (wid >> 1) << 4;
    const int wn32 = (wid & 1) << 5;
    const int gid  = lane >> 2;
    const int tg   = lane & 3;

    const int bm_ = blockIdx.y * 64;

    const int amL = tid >> 3;
    const int akq = (tid & 7) << 2;
    const int aj  = tid & 7;
    const int bkL = tid >> 4;
    const int bnb = (tid & 15) << 2;

    const int r0 = bm_ + wm16 + gid;
    const int r1 = r0 + 8;

    float avv[2][4], bvv[2][4];

    auto sts = [&](int buf) {
        #pragma unroll
        for (int half = 0; half < 2; half++) {
            const int mL = amL + half * 32;
            #pragma unroll
            for (int j = 0; j < 4; j++)
                As[buf][mL][j * 8 + aj] = tf32r(avv[half][j]);
        }
        #pragma unroll
        for (int half = 0; half < 2; half++) {
            const int kL = bkL + half * 16;
            const int pB = (kL & 3) * 8 + (kL >> 2);
            #pragma unroll
            for (int j = 0; j < 4; j++)
                Bs[buf][bnb + j][pB] = tf32r(bvv[half][j]);
        }
    };

    // =============== Phase A: dual GEMM mu|lv, K=523 ===============
    {
        constexpr int Ktot = FRAME + HIDDEN;            // 523
        constexpr int NT   = (Ktot + BK - 1) / BK;      // 17

        auto ldgA = [&](int t) {
            const int kt = t * BK;
            #pragma unroll
            for (int half = 0; half < 2; half++) {
                const int m = bm_ + amL + half * 32;
                #pragma unroll
                for (int j = 0; j < 4; j++) {
                    const int ig = kt + akq + j;
                    float val = 0.f;
                    if (ig < Ktot)
                        val = (ig < FRAME) ? __ldg(&x[m * FRAME + ig])
                                           : __ldg(&h2[m * HIDDEN + (ig - FRAME)]);
                    avv[half][j] = val;
                }
            }
        };
        auto ldgB = [&](int t) {
            const int kt = t * BK;
            #pragma unroll
            for (int half = 0; half < 2; half++) {
                const int kg = kt + bkL + half * 16;
                const bool kok = kg < Ktot;
                #pragma unroll
                for (int j = 0; j < 4; j++) {
                    const int nl = bnb + j;
                    float val = 0.f;
                    if (kok)
                        val = (nl < 32) ? __ldg(&wmu[kg * 32 + nl])
                                        : __ldg(&wlv[kg * 32 + (nl - 32)]);
                    bvv[half][j] = val;
                }
            }
        };

        float acc[4][4] = {};
        ldgA(0); ldgB(0);
        sts(0);
        __syncthreads();

        for (int t = 0; t < NT; t++) {
            const int cur = t & 1;
            const bool more = (t + 1 < NT);
            if (more) { ldgA(t + 1); ldgB(t + 1); }

            LOAD_FRAGS(As[cur], Bs[cur])
            MMA_TILE(acc)

            if (more) sts(1 - cur);
            __syncthreads();
        }

        // epilogue: mu/lv out + smem (overlays on As[0]/Bs[0])
        float* muS = &As[0][0][0];
        float* lvS = &Bs[0][0][0];

        #pragma unroll
        for (int t = 0; t < 4; t++) {
            #pragma unroll
            for (int q = 0; q < 4; q++) {
                const int r  = (q < 2) ? r0 : r1;
                const int rL = r - bm_;
                const int colL = wn32 + (t << 3) + (tg << 1) + (q & 1);
                if (colL < 32) {
                    const float m_ = acc[t][q] + __ldg(&bmu[colL]);
                    mu_out[r * 32 + colL] = m_;
                    muS[rL * 33 + colL] = m_;
                } else {
                    const int cl = colL - 32;
                    const float l_ = acc[t][q] + __ldg(&blv[cl]);
                    lv_out[r * 32 + cl] = l_;
                    lvS[rL * 33 + cl] = l_;
                }
            }
        }
        __syncthreads();

        // z = mu + eps*exp(0.5*lv) -> zsm + q0/q1/q2
        for (int e = tid; e < 64 * 32; e += 256) {
            const int rL = e >> 5, cl = e & 31;
            const int r = bm_ + rL;
            const float zv = fmaf(__ldg(&epsv[r * 32 + cl]),
                                  expf(0.5f * lvS[rL * 33 + cl]), muS[rL * 33 + cl]);
            zsm[rL][cl] = zv;
            q0[r * 320 + cl] = zv;
            q1[r * 288 + cl] = zv;
            q2[r * 288 + cl] = zv;
        }
        __syncthreads();
    }

    // =============== Phase B: gate0 GEMM, K=299, N=64 ===============
    {
        constexpr int Ktot = IN0;                        // 299
        constexpr int NT   = (Ktot + BK - 1) / BK;       // 10

        auto ldgA = [&](int t) {
            const int kt = t * BK;
            #pragma unroll
            for (int half = 0; half < 2; half++) {
                const int mL = amL + half * 32;
                const int m  = bm_ + mL;
                #pragma unroll
                for (int j = 0; j < 4; j++) {
                    const int ig = kt + akq + j;
                    float val = 0.f;
                    if (ig < 32)            val = zsm[mL][ig];
                    else if (ig < Ktot)     val = __ldg(&cc[m * FRAME + (ig - 32)]);
                    avv[half][j] = val;
                }
            }
        };
        auto ldgB = [&](int t) {
            const int kt = t * BK;
            #pragma unroll
            for (int half = 0; half < 2; half++) {
                const int kg = kt + bkL + half * 16;
                const bool kok = kg < Ktot;
                #pragma unroll
                for (int j = 0; j < 4; j++) {
                    const int nl = bnb + j;
                    bvv[half][j] = kok ? __ldg(&gw0[kg * 64 + nl]) : 0.f;
                }
            }
        };

        float acc[4][4] = {};
        ldgA(0); ldgB(0);
        sts(0);
        __syncthreads();

        for (int t = 0; t < NT; t++) {
            const int cur = t & 1;
            const bool more = (t + 1 < NT);
            if (more) { ldgA(t + 1); ldgB(t + 1); }

            LOAD_FRAGS(As[cur], Bs[cur])
            MMA_TILE(acc)

            if (more) sts(1 - cur);
            __syncthreads();
        }

        // epilogue -> g1s (smem)
        #pragma unroll
        for (int t = 0; t < 4; t++) {
            #pragma unroll
            for (int q = 0; q < 4; q++) {
                const int rL = ((q < 2) ? r0 : r1) - bm_;
                const int colL = wn32 + (t << 3) + (tg << 1) + (q & 1);
                g1s[rL][colL] = elu1(acc[t][q] + __ldg(&gb0[colL]));
            }
        }
        __syncthreads();
    }

    // =============== Phase C: gate1 (64x64), w1 overlay on Bs ========
    {
        float* w1f = &Bs[0][0][0];            // 4608 floats total across buffers
        for (int i = tid; i < 64 * 64; i += 256)
            w1f[(i >> 6) * 72 + (i & 63)] = __ldg(&gw1[i]);
        __syncthreads();

        float* g2f = &As[0][0][0];            // [64][65] = 4160 <= 4608
        const int row = tid >> 2;             // 0..63
        const int cs  = tid & 3;
        float a16[16];
        #pragma unroll
        for (int j = 0; j < 16; j++) a16[j] = __ldg(&gb1[cs + (j << 2)]);
        #pragma unroll
        for (int k = 0; k < 64; k++) {
            const float gv = g1s[row][k];
            #pragma unroll
            for (int j = 0; j < 16; j++)
                a16[j] = fmaf(gv, w1f[k * 72 + cs + (j << 2)], a16[j]);
        }
        #pragma unroll
        for (int j = 0; j < 16; j++)
            g2f[row * 65 + cs + (j << 2)] = elu1(a16[j]);
        __syncthreads();
    }

    // =============== Phase D: gate2 + softmax -> coeff ===============
    if (tid < 64) {
        const float* g2f = &As[0][0][0];
        float lg[EXPERTS];
        #pragma unroll
        for (int e = 0; e < EXPERTS; e++) lg[e] = __ldg(&gb2[e]);
        #pragma unroll
        for (int k = 0; k < 64; k++) {
            const float gv = g2f[tid * 65 + k];
            #pragma unroll
            for (int e = 0; e < EXPERTS; e++)
                lg[e] = fmaf(gv, __ldg(&gw2[k * EXPERTS + e]), lg[e]);
        }
        float mx = lg[0];
        #pragma unroll
        for (int e = 1; e < EXPERTS; e++) mx = fmaxf(mx, lg[e]);
        float s = 0.f;
        #pragma unroll
        for (int e = 0; e < EXPERTS; e++) { lg[e] = expf(lg[e] - mx); s += lg[e]; }
        const float inv = 1.f / s;
        #pragma unroll
        for (int e = 0; e < EXPERTS; e++)
            coeff[(bm_ + tid) * EXPERTS + e] = lg[e] * inv;
    }
}

// ============================================================
// Decoder GEMM — packed A, double-buffered, permuted fragment layout.
// ============================================================
template<int N_, int DINR_, int DINP_, int LDA_, int ACT_>
__global__ __launch_bounds__(256) void dec_gemm(
    const float* __restrict__ A,
    const float* __restrict__ coeff,
    const float* __restrict__ W, const float* __restrict__ bias,
    float* __restrict__ C, int ldc)
{
    constexpr int E_  = EXPERTS;
    constexpr int TPE = DINP_ / 32;
    constexpr int NT  = E_ * TPE;
    __shared__ __align__(16) float As[2][64][36];
    __shared__ __align__(16) float Bs[2][64][36];

    const int tid  = threadIdx.x;
    const int lane = tid & 31;
    const int wid  = tid >> 5;
    const int wm16 = (wid >> 1) << 4;
    const int wn32 = (wid & 1) << 5;
    const int gid  = lane >> 2;
    const int tg   = lane & 3;

    const int bm_ = blockIdx.y * 64;
    const int bn_ = blockIdx.x * 64;

    const int amL = tid >> 3;
    const int akq = (tid & 7) << 2;
    const int aj  = tid & 7;
    const int bkL = tid >> 4;
    const int bnb = (tid & 15) << 2;

    const float* Ar0  = A + (bm_ + amL) * LDA_;
    const float* Ar1  = Ar0 + 32 * LDA_;
    const float* cf0p = coeff + (bm_ + amL) * E_;
    const float* cf1p = cf0p + 32 * E_;

    float avv[2][4], bvv[2][4];

    auto ldgA = [&](int t) {
        const int e  = t / TPE;
        const int i0 = (t - e * TPE) * 32 + akq;
        const float c0 = __ldg(&cf0p[e]);
        const float c1 = __ldg(&cf1p[e]);
        const float4 v0 = __ldg(reinterpret_cast<const float4*>(Ar0 + i0));
        const float4 v1 = __ldg(reinterpret_cast<const float4*>(Ar1 + i0));
        avv[0][0] = v0.x * c0; avv[0][1] = v0.y * c0; avv[0][2] = v0.z * c0; avv[0][3] = v0.w * c0;
        avv[1][0] = v1.x * c1; avv[1][1] = v1.y * c1; avv[1][2] = v1.z * c1; avv[1][3] = v1.w * c1;
    };
    auto ldgB = [&](int t) {
        const int e  = t / TPE;
        const int k0 = (t - e * TPE) * 32;
        const float* We = W + (size_t)e * DINR_ * N_;
        #pragma unroll
        for (int half = 0; half < 2; half++) {
            const int kl = k0 + bkL + half * 16;
            const bool kok = (DINR_ == DINP_) || (kl < DINR_);
            if ((N_ % 64) == 0) {
                float4 v = make_float4(0.f, 0.f, 0.f, 0.f);
                if (kok)
                    v = __ldg(reinterpret_cast<const float4*>(We + (size_t)kl * N_ + bn_ + bnb));
                bvv[half][0] = v.x; bvv[half][1] = v.y; bvv[half][2] = v.z; bvv[half][3] = v.w;
            } else {
                #pragma unroll
                for (int j = 0; j < 4; j++) {
                    const int n = bn_ + bnb + j;
                    float v = 0.f;
                    if (kok && n < N_) v = __ldg(&We[(size_t)kl * N_ + n]);
                    bvv[half][j] = v;
                }
            }
        }
    };
    auto sts = [&](int buf) {
        #pragma unroll
        for (int half = 0; half < 2; half++) {
            const int mL = amL + half * 32;
            #pragma unroll
            for (int j = 0; j < 4; j++)
                As[buf][mL][j * 8 + aj] = tf32r(avv[half][j]);
        }
        #pragma unroll
        for (int half = 0; half < 2; half++) {
            const int kL = bkL + half * 16;
            const int pB = (kL & 3) * 8 + (kL >> 2);
            #pragma unroll
            for (int j = 0; j < 4; j++)
                Bs[buf][bnb + j][pB] = tf32r(bvv[half][j]);
        }
    };

    float acc[4][4] = {};

    ldgA(0); ldgB(0);
    sts(0);
    __syncthreads();

    for (int t = 0; t < NT; t++) {
        const int cur = t & 1;
        const bool more = (t + 1 < NT);
        if (more) { ldgA(t + 1); ldgB(t + 1); }

        LOAD_FRAGS(As[cur], Bs[cur])
        MMA_TILE(acc)

        if (more) sts(1 - cur);
        __syncthreads();
    }

    const int r0 = bm_ + wm16 + gid;
    const int r1 = r0 + 8;
    float cf0[E_], cf1[E_];
    #pragma unroll
    for (int e = 0; e < E_; e++) {
        cf0[e] = coeff[r0 * E_ + e];
        cf1[e] = coeff[r1 * E_ + e];
    }

    #pragma unroll
    for (int t = 0; t < 4; t++) {
        #pragma unroll
        for (int q = 0; q < 4; q++) {
            const int r  = (q < 2) ? r0 : r1;
            const int colL = wn32 + (t << 3) + (tg << 1) + (q & 1);
            const int cG = bn_ + colL;
            if ((N_ % 64) == 0 || cG < N_) {
                const float* cf = (q < 2) ? cf0 : cf1;
                float bb = 0.f;
                #pragma unroll
                for (int e = 0; e < E_; e++)
                    bb = fmaf(cf[e], __ldg(&bias[e * N_ + cG]), bb);
                float v = acc[t][q] + bb;
                if (ACT_ == 1) v = elu1(v);
                C[r * ldc + cG] = v;
            }
        }
    }
}

// ---------------- pack kernel: c -> q0 cols [32, 320) ----------------
__global__ void pack_c(const float* __restrict__ c, float* __restrict__ q0)
{
    int idx = blockIdx.x * blockDim.x + threadIdx.x;
    if (idx >= BATCH * 288) return;
    const int r = idx / 288;
    const int col = 32 + idx % 288;     // 32..319
    q0[r * 320 + col] = (col < IN0) ? c[r * FRAME + (col - 32)] : 0.f;
}

// ---------------- launch ----------------
extern "C" void kernel_launch(void* const* d_in, const int* in_sizes, int n_in,
                              void* d_out, int out_size)
{
    const float* x       = (const float*)d_in[0];
    const float* c       = (const float*)d_in[1];
    const float* eps     = (const float*)d_in[2];
    const float* enc_w1  = (const float*)d_in[3];
    const float* enc_b1  = (const float*)d_in[4];
    const float* enc_w2  = (const float*)d_in[5];
    const float* enc_b2  = (const float*)d_in[6];
    const float* enc_wmu = (const float*)d_in[7];
    const float* enc_bmu = (const float*)d_in[8];
    const float* enc_wlv = (const float*)d_in[9];
    const float* enc_blv = (const float*)d_in[10];
    const float* gw0     = (const float*)d_in[11];
    const float* gb0     = (const float*)d_in[12];
    const float* gw1     = (const float*)d_in[13];
    const float* gb1     = (const float*)d_in[14];
    const float* gw2     = (const float*)d_in[15];
    const float* gb2     = (const float*)d_in[16];
    const float* w0      = (const float*)d_in[17];
    const float* b0      = (const float*)d_in[18];
    const float* w1      = (const float*)d_in[19];
    const float* b1      = (const float*)d_in[20];
    const float* w2      = (const float*)d_in[21];
    const float* b2      = (const float*)d_in[22];
    float* out = (float*)d_out;

    float *h1, *h2, *coef, *q0, *q1, *q2;
    cudaGetSymbolAddress((void**)&h1,   g_h1);
    cudaGetSymbolAddress((void**)&h2,   g_h2);
    cudaGetSymbolAddress((void**)&coef, g_coef);
    cudaGetSymbolAddress((void**)&q0,   g_q0);
    cudaGetSymbolAddress((void**)&q1,   g_q1);
    cudaGetSymbolAddress((void**)&q2,   g_q2);

    const dim3 blk(256);
    const dim3 gridH(HIDDEN / 64, BATCH / 64);              // (4, 64)
    const dim3 grid1(1, BATCH / 64);                        // (1, 64)
    const dim3 gridO((OUTD + 63) / 64, BATCH / 64);         // (5, 64)

    // pack c into q0 cols [32,320)
    pack_c<<<(BATCH * 288 + 255) / 256, 256>>>(c, q0);
    // encoder layer 1: h1 = elu([x, c] @ enc_w1 + b1)   K=534
    enc_gemm<HIDDEN, FRAME, 2*FRAME, 1><<<gridH, blk>>>(
        x, FRAME, c, FRAME, enc_w1, enc_b1, h1, HIDDEN);
    // encoder layer 2: h2 = elu([x, h1] @ enc_w2 + b2)  K=523
    enc_gemm<HIDDEN, FRAME, FRAME+HIDDEN, 1><<<gridH, blk>>>(
        x, FRAME, h1, HIDDEN, enc_w2, enc_b2, h2, HIDDEN);
    // mid2: mu/lv + z + gate0 + gate1 + gate2 + softmax (one launch)
    mid2<<<grid1, blk>>>(
        x, h2, enc_wmu, enc_bmu, enc_wlv, enc_blv, eps, c,
        gw0, gb0, gw1, gb1, gw2, gb2,
        out + OFF_MU, out + OFF_LV, q0, q1, q2, coef);
    // MoE decoder layer 0: DIN 299 (pad 320) -> d1 into q1 cols [32,288)
    dec_gemm<HIDDEN, IN0, 320, 320, 1><<<gridH, blk>>>(
        q0, coef, w0, b0, q1 + 32, IN1);
    // MoE decoder layer 1: DIN 288 exact -> d2 into q2 cols [32,288)
    dec_gemm<HIDDEN, IN1, 288, 288, 1><<<gridH, blk>>>(
        q1, coef, w1, b1, q2 + 32, IN1);
    // MoE decoder layer 2 (no act): N=267 -> output
    dec_gemm<OUTD, IN1, 288, 288, 0><<<gridO, blk>>>(
        q2, coef, w2, b2, out, OUTD);
}

// round 14
// speedup vs baseline: 1.2257x; 1.2257x over previous
#include <cuda_runtime.h>
#include <cstdint>

// ---------------- problem constants ----------------
#define BATCH   4096
#define FRAME   267
#define LATENT  32
#define HIDDEN  256
#define GATE_H  64
#define EXPERTS 6
#define IN0     (LATENT + FRAME)    // 299
#define IN1     (LATENT + HIDDEN)   // 288
#define OUTD    FRAME               // 267

#define OFF_MU  (BATCH * OUTD)
#define OFF_LV  (OFF_MU + BATCH * LATENT)

// ---------------- scratch (allocation-free) ----------------
__device__ float g_h1[BATCH * HIDDEN];
__device__ float g_h2[BATCH * HIDDEN];
__device__ float g_coef[BATCH * EXPERTS];
// packed decoder inputs (16B-aligned rows)
__device__ __align__(16) float g_q0[BATCH * 320];   // [z | c | 0pad]
__device__ __align__(16) float g_q1[BATCH * 288];   // [z | d1]
__device__ __align__(16) float g_q2[BATCH * 288];   // [z | d2]

__device__ __forceinline__ float elu1(float x) { return x > 0.f ? x : expm1f(x); }

__device__ __forceinline__ float tf32r(float x) {
    float y;
    asm("cvt.rna.tf32.f32 %0, %1;" : "=f"(y) : "f"(x));
    return y;
}

#define BK 32

// ============================================================
// Encoder/gate GEMM — 32x64x32 tile, 128 threads, 4 warps (2m x 2n),
// warp tile m16n32. Same proven consumer (scalar LDS, strides 36/72,
// conflict-free) + double buffering. Grid doubles vs 64-row tiles.
// ============================================================
template<int N_, int K0_, int DIN_, int ACT_>
__global__ __launch_bounds__(128) void enc_gemm(
    const float* __restrict__ A0, int lda0,
    const float* __restrict__ A1, int lda1,
    const float* __restrict__ W, const float* __restrict__ bias,
    float* __restrict__ C, int ldc)
{
    constexpr int Ktot = DIN_;
    constexpr int NT   = (Ktot + BK - 1) / BK;
    __shared__ __align__(16) float As[2][32][36];
    __shared__ __align__(16) float Bs[2][32][72];

    const int tid  = threadIdx.x;
    const int lane = tid & 31;
    const int wid  = tid >> 5;          // 0..3
    const int wm16 = (wid & 1) << 4;    // 0,16
    const int wn32 = (wid >> 1) << 5;   // 0,32
    const int gid  = lane >> 2;
    const int tg   = lane & 3;

    const int bm_ = blockIdx.y * 32;
    const int bn_ = blockIdx.x * 64;

    // producers: A 32x32/128thr = 8 ea ; B 32x64/128thr = 16 ea
    const int amL = tid >> 2;           // 0..31
    const int ak8 = (tid & 3) << 3;     // 0,8,16,24
    const int bkq = tid >> 4;           // 0..7 (4 quarters: +0,+8,+16,+24)
    const int bnb = (tid & 15) << 2;    // 0..60

    float avv[8], bvv[4][4];

    auto ldgA = [&](int t) {
        const int kt = t * BK;
        const int m  = bm_ + amL;
        #pragma unroll
        for (int j = 0; j < 8; j++) {
            const int ig = kt + ak8 + j;
            float val = 0.f;
            if ((Ktot % BK == 0) || ig < Ktot)
                val = (ig < K0_) ? __ldg(&A0[m * lda0 + ig])
                                 : __ldg(&A1[m * lda1 + (ig - K0_)]);
            avv[j] = val;
        }
    };
    auto ldgB = [&](int t) {
        const int kt = t * BK;
        #pragma unroll
        for (int q = 0; q < 4; q++) {
            const int kg = kt + bkq + q * 8;
            const bool kok = (Ktot % BK == 0) || (kg < Ktot);
            #pragma unroll
            for (int j = 0; j < 4; j++) {
                const int n = bn_ + bnb + j;
                float val = 0.f;
                if (kok && ((N_ % 64) == 0 || n < N_))
                    val = __ldg(&W[(size_t)kg * N_ + n]);
                bvv[q][j] = val;
            }
        }
    };
    auto sts = [&](int buf) {
        #pragma unroll
        for (int j = 0; j < 8; j++)
            As[buf][amL][ak8 + j] = tf32r(avv[j]);
        #pragma unroll
        for (int q = 0; q < 4; q++)
            #pragma unroll
            for (int j = 0; j < 4; j++)
                Bs[buf][bkq + q * 8][bnb + j] = tf32r(bvv[q][j]);
    };

    float acc[4][4] = {};

    ldgA(0); ldgB(0);
    sts(0);
    __syncthreads();

    for (int t = 0; t < NT; t++) {
        const int cur = t & 1;
        const bool more = (t + 1 < NT);
        if (more) { ldgA(t + 1); ldgB(t + 1); }

        #pragma unroll
        for (int ks = 0; ks < 4; ks++) {
            const int kk = ks << 3;
            uint32_t a0 = __float_as_uint(As[cur][wm16 + gid    ][kk + tg    ]);
            uint32_t a1 = __float_as_uint(As[cur][wm16 + gid + 8][kk + tg    ]);
            uint32_t a2 = __float_as_uint(As[cur][wm16 + gid    ][kk + tg + 4]);
            uint32_t a3 = __float_as_uint(As[cur][wm16 + gid + 8][kk + tg + 4]);
            #pragma unroll
            for (int t4 = 0; t4 < 4; t4++) {
                const int col = wn32 + (t4 << 3) + gid;
                uint32_t b0 = __float_as_uint(Bs[cur][kk + tg    ][col]);
                uint32_t b1 = __float_as_uint(Bs[cur][kk + tg + 4][col]);
                asm volatile(
                    "mma.sync.aligned.m16n8k8.row.col.f32.tf32.tf32.f32 "
                    "{%0,%1,%2,%3}, {%4,%5,%6,%7}, {%8,%9}, {%0,%1,%2,%3};\n"
                    : "+f"(acc[t4][0]), "+f"(acc[t4][1]),
                      "+f"(acc[t4][2]), "+f"(acc[t4][3])
                    : "r"(a0), "r"(a1), "r"(a2), "r"(a3), "r"(b0), "r"(b1));
            }
        }
        if (more) sts(1 - cur);
        __syncthreads();
    }

    const int r0 = bm_ + wm16 + gid;
    const int r1 = r0 + 8;
    #pragma unroll
    for (int t = 0; t < 4; t++) {
        #pragma unroll
        for (int q = 0; q < 4; q++) {
            const int r  = (q < 2) ? r0 : r1;
            const int colL = wn32 + (t << 3) + (tg << 1) + (q & 1);
            const int cG = bn_ + colL;
            if ((N_ % 64) == 0 || cG < N_) {
                float v = acc[t][q] + __ldg(&bias[cG]);
                if (ACT_ == 1) v = elu1(v);
                C[r * ldc + cG] = v;
            }
        }
    }
}

// ============================================================
// mid2 — R12-passing version VERBATIM: dual GEMM (mu|lv, K=523) + z
// + gate0 GEMM (K=299, z from smem zsm / c from read-only input)
// + gate1 + gate2 + softmax. 64 rows/block, 256 thr, grid (1,64).
// ============================================================
__global__ __launch_bounds__(256) void mid2(
    const float* __restrict__ x,   const float* __restrict__ h2,
    const float* __restrict__ wmu, const float* __restrict__ bmu,
    const float* __restrict__ wlv, const float* __restrict__ blv,
    const float* __restrict__ epsv, const float* __restrict__ cc,
    const float* __restrict__ gw0, const float* __restrict__ gb0,
    const float* __restrict__ gw1, const float* __restrict__ gb1,
    const float* __restrict__ gw2, const float* __restrict__ gb2,
    float* __restrict__ mu_out, float* __restrict__ lv_out,
    float* __restrict__ q0, float* __restrict__ q1, float* __restrict__ q2,
    float* __restrict__ coeff)
{
    __shared__ float As[2][64][36];     // overlays: muS, g2s
    __shared__ float Bs[2][32][72];     // overlays: lvS, w1s
    __shared__ float g1s[64][65];
    __shared__ float zsm[64][33];

    const int tid  = threadIdx.x;
    const int lane = tid & 31;
    const int wid  = tid >> 5;
    const int wm16 = (wid >> 1) << 4;
    const int wn32 = (wid & 1) << 5;
    const int gid  = lane >> 2;
    const int tg   = lane & 3;

    const int bm_ = blockIdx.y * 64;

    const int amL = tid >> 3;
    const int akq = (tid & 7) << 2;
    const int bkL = tid >> 4;
    const int bnb = (tid & 15) << 2;

    const int r0 = bm_ + wm16 + gid;
    const int r1 = r0 + 8;

    float avv[2][4], bvv[2][4];

    auto sts = [&](int buf) {
        #pragma unroll
        for (int half = 0; half < 2; half++) {
            const int mL = amL + half * 32;
            #pragma unroll
            for (int j = 0; j < 4; j++)
                As[buf][mL][akq + j] = tf32r(avv[half][j]);
        }
        #pragma unroll
        for (int half = 0; half < 2; half++) {
            const int kL = bkL + half * 16;
            #pragma unroll
            for (int j = 0; j < 4; j++)
                Bs[buf][kL][bnb + j] = tf32r(bvv[half][j]);
        }
    };

    // Phase A: dual GEMM mu|lv, K=523
    {
        constexpr int Ktot = FRAME + HIDDEN;
        constexpr int NT   = (Ktot + BK - 1) / BK;

        auto ldgA = [&](int t) {
            const int kt = t * BK;
            #pragma unroll
            for (int half = 0; half < 2; half++) {
                const int m = bm_ + amL + half * 32;
                #pragma unroll
                for (int j = 0; j < 4; j++) {
                    const int ig = kt + akq + j;
                    float val = 0.f;
                    if (ig < Ktot)
                        val = (ig < FRAME) ? __ldg(&x[m * FRAME + ig])
                                           : __ldg(&h2[m * HIDDEN + (ig - FRAME)]);
                    avv[half][j] = val;
                }
            }
        };
        auto ldgB = [&](int t) {
            const int kt = t * BK;
            #pragma unroll
            for (int half = 0; half < 2; half++) {
                const int kg = kt + bkL + half * 16;
                const bool kok = kg < Ktot;
                #pragma unroll
                for (int j = 0; j < 4; j++) {
                    const int nl = bnb + j;
                    float val = 0.f;
                    if (kok)
                        val = (nl < 32) ? __ldg(&wmu[kg * 32 + nl])
                                        : __ldg(&wlv[kg * 32 + (nl - 32)]);
                    bvv[half][j] = val;
                }
            }
        };

        float acc[4][4] = {};
        ldgA(0); ldgB(0);
        sts(0);
        __syncthreads();

        for (int t = 0; t < NT; t++) {
            const int cur = t & 1;
            const bool more = (t + 1 < NT);
            if (more) { ldgA(t + 1); ldgB(t + 1); }

            #pragma unroll
            for (int ks = 0; ks < 4; ks++) {
                const int kk = ks << 3;
                uint32_t a0 = __float_as_uint(As[cur][wm16 + gid    ][kk + tg    ]);
                uint32_t a1 = __float_as_uint(As[cur][wm16 + gid + 8][kk + tg    ]);
                uint32_t a2 = __float_as_uint(As[cur][wm16 + gid    ][kk + tg + 4]);
                uint32_t a3 = __float_as_uint(As[cur][wm16 + gid + 8][kk + tg + 4]);
                #pragma unroll
                for (int t4 = 0; t4 < 4; t4++) {
                    const int col = wn32 + (t4 << 3) + gid;
                    uint32_t b0 = __float_as_uint(Bs[cur][kk + tg    ][col]);
                    uint32_t b1 = __float_as_uint(Bs[cur][kk + tg + 4][col]);
                    asm volatile(
                        "mma.sync.aligned.m16n8k8.row.col.f32.tf32.tf32.f32 "
                        "{%0,%1,%2,%3}, {%4,%5,%6,%7}, {%8,%9}, {%0,%1,%2,%3};\n"
                        : "+f"(acc[t4][0]), "+f"(acc[t4][1]),
                          "+f"(acc[t4][2]), "+f"(acc[t4][3])
                        : "r"(a0), "r"(a1), "r"(a2), "r"(a3), "r"(b0), "r"(b1));
                }
            }
            if (more) sts(1 - cur);
            __syncthreads();
        }

        float* muS = &As[0][0][0];
        float* lvS = &Bs[0][0][0];

        #pragma unroll
        for (int t = 0; t < 4; t++) {
            #pragma unroll
            for (int q = 0; q < 4; q++) {
                const int r  = (q < 2) ? r0 : r1;
                const int rL = r - bm_;
                const int colL = wn32 + (t << 3) + (tg << 1) + (q & 1);
                if (colL < 32) {
                    const float m_ = acc[t][q] + __ldg(&bmu[colL]);
                    mu_out[r * 32 + colL] = m_;
                    muS[rL * 33 + colL] = m_;
                } else {
                    const int cl = colL - 32;
                    const float l_ = acc[t][q] + __ldg(&blv[cl]);
                    lv_out[r * 32 + cl] = l_;
                    lvS[rL * 33 + cl] = l_;
                }
            }
        }
        __syncthreads();

        for (int e = tid; e < 64 * 32; e += 256) {
            const int rL = e >> 5, cl = e & 31;
            const int r = bm_ + rL;
            const float zv = fmaf(__ldg(&epsv[r * 32 + cl]),
                                  expf(0.5f * lvS[rL * 33 + cl]), muS[rL * 33 + cl]);
            zsm[rL][cl] = zv;
            q0[r * 320 + cl] = zv;
            q1[r * 288 + cl] = zv;
            q2[r * 288 + cl] = zv;
        }
        __syncthreads();
    }

    // Phase B: gate0 GEMM, K=299, N=64
    {
        constexpr int Ktot = IN0;
        constexpr int NT   = (Ktot + BK - 1) / BK;

        auto ldgA = [&](int t) {
            const int kt = t * BK;
            #pragma unroll
            for (int half = 0; half < 2; half++) {
                const int mL = amL + half * 32;
                const int m  = bm_ + mL;
                #pragma unroll
                for (int j = 0; j < 4; j++) {
                    const int ig = kt + akq + j;
                    float val = 0.f;
                    if (ig < 32)            val = zsm[mL][ig];
                    else if (ig < Ktot)     val = __ldg(&cc[m * FRAME + (ig - 32)]);
                    avv[half][j] = val;
                }
            }
        };
        auto ldgB = [&](int t) {
            const int kt = t * BK;
            #pragma unroll
            for (int half = 0; half < 2; half++) {
                const int kg = kt + bkL + half * 16;
                const bool kok = kg < Ktot;
                #pragma unroll
                for (int j = 0; j < 4; j++) {
                    const int nl = bnb + j;
                    bvv[half][j] = kok ? __ldg(&gw0[kg * 64 + nl]) : 0.f;
                }
            }
        };

        float acc[4][4] = {};
        ldgA(0); ldgB(0);
        sts(0);
        __syncthreads();

        for (int t = 0; t < NT; t++) {
            const int cur = t & 1;
            const bool more = (t + 1 < NT);
            if (more) { ldgA(t + 1); ldgB(t + 1); }

            #pragma unroll
            for (int ks = 0; ks < 4; ks++) {
                const int kk = ks << 3;
                uint32_t a0 = __float_as_uint(As[cur][wm16 + gid    ][kk + tg    ]);
                uint32_t a1 = __float_as_uint(As[cur][wm16 + gid + 8][kk + tg    ]);
                uint32_t a2 = __float_as_uint(As[cur][wm16 + gid    ][kk + tg + 4]);
                uint32_t a3 = __float_as_uint(As[cur][wm16 + gid + 8][kk + tg + 4]);
                #pragma unroll
                for (int t4 = 0; t4 < 4; t4++) {
                    const int col = wn32 + (t4 << 3) + gid;
                    uint32_t b0 = __float_as_uint(Bs[cur][kk + tg    ][col]);
                    uint32_t b1 = __float_as_uint(Bs[cur][kk + tg + 4][col]);
                    asm volatile(
                        "mma.sync.aligned.m16n8k8.row.col.f32.tf32.tf32.f32 "
                        "{%0,%1,%2,%3}, {%4,%5,%6,%7}, {%8,%9}, {%0,%1,%2,%3};\n"
                        : "+f"(acc[t4][0]), "+f"(acc[t4][1]),
                          "+f"(acc[t4][2]), "+f"(acc[t4][3])
                        : "r"(a0), "r"(a1), "r"(a2), "r"(a3), "r"(b0), "r"(b1));
                }
            }
            if (more) sts(1 - cur);
            __syncthreads();
        }

        #pragma unroll
        for (int t = 0; t < 4; t++) {
            #pragma unroll
            for (int q = 0; q < 4; q++) {
                const int rL = ((q < 2) ? r0 : r1) - bm_;
                const int colL = wn32 + (t << 3) + (tg << 1) + (q & 1);
                g1s[rL][colL] = elu1(acc[t][q] + __ldg(&gb0[colL]));
            }
        }
        __syncthreads();
    }

    // Phase C: gate1 (64x64), w1 overlay on Bs
    {
        float* w1f = &Bs[0][0][0];
        for (int i = tid; i < 64 * 64; i += 256)
            w1f[(i >> 6) * 72 + (i & 63)] = __ldg(&gw1[i]);
        __syncthreads();

        float* g2f = &As[0][0][0];
        const int row = tid >> 2;
        const int cs  = tid & 3;
        float a16[16];
        #pragma unroll
        for (int j = 0; j < 16; j++) a16[j] = __ldg(&gb1[cs + (j << 2)]);
        #pragma unroll
        for (int k = 0; k < 64; k++) {
            const float gv = g1s[row][k];
            #pragma unroll
            for (int j = 0; j < 16; j++)
                a16[j] = fmaf(gv, w1f[k * 72 + cs + (j << 2)], a16[j]);
        }
        #pragma unroll
        for (int j = 0; j < 16; j++)
            g2f[row * 65 + cs + (j << 2)] = elu1(a16[j]);
        __syncthreads();
    }

    // Phase D: gate2 + softmax -> coeff
    if (tid < 64) {
        const float* g2f = &As[0][0][0];
        float lg[EXPERTS];
        #pragma unroll
        for (int e = 0; e < EXPERTS; e++) lg[e] = __ldg(&gb2[e]);
        #pragma unroll
        for (int k = 0; k < 64; k++) {
            const float gv = g2f[tid * 65 + k];
            #pragma unroll
            for (int e = 0; e < EXPERTS; e++)
                lg[e] = fmaf(gv, __ldg(&gw2[k * EXPERTS + e]), lg[e]);
        }
        float mx = lg[0];
        #pragma unroll
        for (int e = 1; e < EXPERTS; e++) mx = fmaxf(mx, lg[e]);
        float s = 0.f;
        #pragma unroll
        for (int e = 0; e < EXPERTS; e++) { lg[e] = expf(lg[e] - mx); s += lg[e]; }
        const float inv = 1.f / s;
        #pragma unroll
        for (int e = 0; e < EXPERTS; e++)
            coeff[(bm_ + tid) * EXPERTS + e] = lg[e] * inv;
    }
}

// ============================================================
// Decoder GEMM — 32x64x32 tile, 128 threads, 4 warps (2m x 2n),
// packed aligned A (2x LDG.128 + 1 coeff per thread per tile),
// double-buffered, proven consumer.
// ============================================================
template<int N_, int DINR_, int DINP_, int LDA_, int ACT_>
__global__ __launch_bounds__(128) void dec_gemm(
    const float* __restrict__ A,
    const float* __restrict__ coeff,
    const float* __restrict__ W, const float* __restrict__ bias,
    float* __restrict__ C, int ldc)
{
    constexpr int E_  = EXPERTS;
    constexpr int TPE = DINP_ / 32;
    constexpr int NT  = E_ * TPE;
    __shared__ __align__(16) float As[2][32][36];
    __shared__ __align__(16) float Bs[2][32][72];

    const int tid  = threadIdx.x;
    const int lane = tid & 31;
    const int wid  = tid >> 5;
    const int wm16 = (wid & 1) << 4;
    const int wn32 = (wid >> 1) << 5;
    const int gid  = lane >> 2;
    const int tg   = lane & 3;

    const int bm_ = blockIdx.y * 32;
    const int bn_ = blockIdx.x * 64;

    const int amL = tid >> 2;           // 0..31
    const int ak8 = (tid & 3) << 3;     // 0,8,16,24
    const int bkq = tid >> 4;           // 0..7
    const int bnb = (tid & 15) << 2;    // 0..60

    const float* Ar  = A + (bm_ + amL) * LDA_;
    const float* cfp = coeff + (bm_ + amL) * E_;

    float avv[8], bvv[4][4];

    auto ldgA = [&](int t) {
        const int e  = t / TPE;
        const int i0 = (t - e * TPE) * 32 + ak8;
        const float cf = __ldg(&cfp[e]);
        const float4 v0 = __ldg(reinterpret_cast<const float4*>(Ar + i0));
        const float4 v1 = __ldg(reinterpret_cast<const float4*>(Ar + i0 + 4));
        avv[0] = v0.x * cf; avv[1] = v0.y * cf; avv[2] = v0.z * cf; avv[3] = v0.w * cf;
        avv[4] = v1.x * cf; avv[5] = v1.y * cf; avv[6] = v1.z * cf; avv[7] = v1.w * cf;
    };
    auto ldgB = [&](int t) {
        const int e  = t / TPE;
        const int k0 = (t - e * TPE) * 32;
        const float* We = W + (size_t)e * DINR_ * N_;
        #pragma unroll
        for (int q = 0; q < 4; q++) {
            const int kl = k0 + bkq + q * 8;
            const bool kok = (DINR_ == DINP_) || (kl < DINR_);
            if ((N_ % 64) == 0) {
                float4 v = make_float4(0.f, 0.f, 0.f, 0.f);
                if (kok)
                    v = __ldg(reinterpret_cast<const float4*>(We + (size_t)kl * N_ + bn_ + bnb));
                bvv[q][0] = v.x; bvv[q][1] = v.y; bvv[q][2] = v.z; bvv[q][3] = v.w;
            } else {
                #pragma unroll
                for (int j = 0; j < 4; j++) {
                    const int n = bn_ + bnb + j;
                    float v = 0.f;
                    if (kok && n < N_) v = __ldg(&We[(size_t)kl * N_ + n]);
                    bvv[q][j] = v;
                }
            }
        }
    };
    auto sts = [&](int buf) {
        {
            const float4 t0 = make_float4(tf32r(avv[0]), tf32r(avv[1]),
                                          tf32r(avv[2]), tf32r(avv[3]));
            const float4 t1 = make_float4(tf32r(avv[4]), tf32r(avv[5]),
                                          tf32r(avv[6]), tf32r(avv[7]));
            *reinterpret_cast<float4*>(&As[buf][amL][ak8])     = t0;
            *reinterpret_cast<float4*>(&As[buf][amL][ak8 + 4]) = t1;
        }
        #pragma unroll
        for (int q = 0; q < 4; q++) {
            const float4 t4 = make_float4(tf32r(bvv[q][0]), tf32r(bvv[q][1]),
                                          tf32r(bvv[q][2]), tf32r(bvv[q][3]));
            *reinterpret_cast<float4*>(&Bs[buf][bkq + q * 8][bnb]) = t4;
        }
    };

    float acc[4][4] = {};

    ldgA(0); ldgB(0);
    sts(0);
    __syncthreads();

    for (int t = 0; t < NT; t++) {
        const int cur = t & 1;
        const bool more = (t + 1 < NT);
        if (more) { ldgA(t + 1); ldgB(t + 1); }

        #pragma unroll
        for (int ks = 0; ks < 4; ks++) {
            const int kk = ks << 3;
            uint32_t a0 = __float_as_uint(As[cur][wm16 + gid    ][kk + tg    ]);
            uint32_t a1 = __float_as_uint(As[cur][wm16 + gid + 8][kk + tg    ]);
            uint32_t a2 = __float_as_uint(As[cur][wm16 + gid    ][kk + tg + 4]);
            uint32_t a3 = __float_as_uint(As[cur][wm16 + gid + 8][kk + tg + 4]);
            #pragma unroll
            for (int t4i = 0; t4i < 4; t4i++) {
                const int col = wn32 + (t4i << 3) + gid;
                uint32_t b0 = __float_as_uint(Bs[cur][kk + tg    ][col]);
                uint32_t b1 = __float_as_uint(Bs[cur][kk + tg + 4][col]);
                asm volatile(
                    "mma.sync.aligned.m16n8k8.row.col.f32.tf32.tf32.f32 "
                    "{%0,%1,%2,%3}, {%4,%5,%6,%7}, {%8,%9}, {%0,%1,%2,%3};\n"
                    : "+f"(acc[t4i][0]), "+f"(acc[t4i][1]),
                      "+f"(acc[t4i][2]), "+f"(acc[t4i][3])
                    : "r"(a0), "r"(a1), "r"(a2), "r"(a3), "r"(b0), "r"(b1));
            }
        }
        if (more) sts(1 - cur);
        __syncthreads();
    }

    const int r0 = bm_ + wm16 + gid;
    const int r1 = r0 + 8;
    float cf0[E_], cf1[E_];
    #pragma unroll
    for (int e = 0; e < E_; e++) {
        cf0[e] = coeff[r0 * E_ + e];
        cf1[e] = coeff[r1 * E_ + e];
    }

    #pragma unroll
    for (int t = 0; t < 4; t++) {
        #pragma unroll
        for (int q = 0; q < 4; q++) {
            const int r  = (q < 2) ? r0 : r1;
            const int colL = wn32 + (t << 3) + (tg << 1) + (q & 1);
            const int cG = bn_ + colL;
            if ((N_ % 64) == 0 || cG < N_) {
                const float* cf = (q < 2) ? cf0 : cf1;
                float bb = 0.f;
                #pragma unroll
                for (int e = 0; e < E_; e++)
                    bb = fmaf(cf[e], __ldg(&bias[e * N_ + cG]), bb);
                float v = acc[t][q] + bb;
                if (ACT_ == 1) v = elu1(v);
                C[r * ldc + cG] = v;
            }
        }
    }
}

// ---------------- pack kernel: c -> q0 cols [32, 320) ----------------
__global__ void pack_c(const float* __restrict__ c, float* __restrict__ q0)
{
    int idx = blockIdx.x * blockDim.x + threadIdx.x;
    if (idx >= BATCH * 288) return;
    const int r = idx / 288;
    const int col = 32 + idx % 288;     // 32..319
    q0[r * 320 + col] = (col < IN0) ? c[r * FRAME + (col - 32)] : 0.f;
}

// ---------------- launch ----------------
extern "C" void kernel_launch(void* const* d_in, const int* in_sizes, int n_in,
                              void* d_out, int out_size)
{
    const float* x       = (const float*)d_in[0];
    const float* c       = (const float*)d_in[1];
    const float* eps     = (const float*)d_in[2];
    const float* enc_w1  = (const float*)d_in[3];
    const float* enc_b1  = (const float*)d_in[4];
    const float* enc_w2  = (const float*)d_in[5];
    const float* enc_b2  = (const float*)d_in[6];
    const float* enc_wmu = (const float*)d_in[7];
    const float* enc_bmu = (const float*)d_in[8];
    const float* enc_wlv = (const float*)d_in[9];
    const float* enc_blv = (const float*)d_in[10];
    const float* gw0     = (const float*)d_in[11];
    const float* gb0     = (const float*)d_in[12];
    const float* gw1     = (const float*)d_in[13];
    const float* gb1     = (const float*)d_in[14];
    const float* gw2     = (const float*)d_in[15];
    const float* gb2     = (const float*)d_in[16];
    const float* w0      = (const float*)d_in[17];
    const float* b0      = (const float*)d_in[18];
    const float* w1      = (const float*)d_in[19];
    const float* b1      = (const float*)d_in[20];
    const float* w2      = (const float*)d_in[21];
    const float* b2      = (const float*)d_in[22];
    float* out = (float*)d_out;

    float *h1, *h2, *coef, *q0, *q1, *q2;
    cudaGetSymbolAddress((void**)&h1,   g_h1);
    cudaGetSymbolAddress((void**)&h2,   g_h2);
    cudaGetSymbolAddress((void**)&coef, g_coef);
    cudaGetSymbolAddress((void**)&q0,   g_q0);
    cudaGetSymbolAddress((void**)&q1,   g_q1);
    cudaGetSymbolAddress((void**)&q2,   g_q2);

    const dim3 blk128(128);
    const dim3 blk256(256);
    const dim3 gridH(HIDDEN / 64, BATCH / 32);              // (4, 128) = 512
    const dim3 grid1(1, BATCH / 64);                        // (1, 64)
    const dim3 gridO((OUTD + 63) / 64, BATCH / 32);         // (5, 128) = 640

    // pack c into q0 cols [32,320)
    pack_c<<<(BATCH * 288 + 255) / 256, 256>>>(c, q0);
    // encoder layer 1: h1 = elu([x, c] @ enc_w1 + b1)   K=534
    enc_gemm<HIDDEN, FRAME, 2*FRAME, 1><<<gridH, blk128>>>(
        x, FRAME, c, FRAME, enc_w1, enc_b1, h1, HIDDEN);
    // encoder layer 2: h2 = elu([x, h1] @ enc_w2 + b2)  K=523
    enc_gemm<HIDDEN, FRAME, FRAME+HIDDEN, 1><<<gridH, blk128>>>(
        x, FRAME, h1, HIDDEN, enc_w2, enc_b2, h2, HIDDEN);
    // mid2: mu/lv + z + gate0 + gate1 + gate2 + softmax (one launch)
    mid2<<<grid1, blk256>>>(
        x, h2, enc_wmu, enc_bmu, enc_wlv, enc_blv, eps, c,
        gw0, gb0, gw1, gb1, gw2, gb2,
        out + OFF_MU, out + OFF_LV, q0, q1, q2, coef);
    // MoE decoder layer 0: DIN 299 (pad 320) -> d1 into q1 cols [32,288)
    dec_gemm<HIDDEN, IN0, 320, 320, 1><<<gridH, blk128>>>(
        q0, coef, w0, b0, q1 + 32, IN1);
    // MoE decoder layer 1: DIN 288 exact -> d2 into q2 cols [32,288)
    dec_gemm<HIDDEN, IN1, 288, 288, 1><<<gridH, blk128>>>(
        q1, coef, w1, b1, q2 + 32, IN1);
    // MoE decoder layer 2 (no act): N=267 -> output
    dec_gemm<OUTD, IN1, 288, 288, 0><<<gridO, blk128>>>(
        q2, coef, w2, b2, out, OUTD);
}

// round 15
// speedup vs baseline: 1.4222x; 1.1604x over previous
#include <cuda_runtime.h>
#include <cstdint>

// ---------------- problem constants ----------------
#define BATCH   4096
#define FRAME   267
#define LATENT  32
#define HIDDEN  256
#define GATE_H  64
#define EXPERTS 6
#define IN0     (LATENT + FRAME)    // 299
#define IN1     (LATENT + HIDDEN)   // 288
#define OUTD    FRAME               // 267

#define OFF_MU  (BATCH * OUTD)
#define OFF_LV  (OFF_MU + BATCH * LATENT)

// ---------------- scratch (allocation-free) ----------------
__device__ float g_h1[BATCH * HIDDEN];
__device__ float g_h2[BATCH * HIDDEN];
__device__ float g_coef[BATCH * EXPERTS];
// packed decoder inputs (16B-aligned rows)
__device__ __align__(16) float g_q0[BATCH * 320];   // [z | c | 0pad]
__device__ __align__(16) float g_q1[BATCH * 288];   // [z | d1]
__device__ __align__(16) float g_q2[BATCH * 288];   // [z | d2]

__device__ __forceinline__ float elu1(float x) { return x > 0.f ? x : expm1f(x); }

__device__ __forceinline__ float tf32r(float x) {
    float y;
    asm("cvt.rna.tf32.f32 %0, %1;" : "=f"(y) : "f"(x));
    return y;
}

#define BK 32

// ============================================================
// Encoder GEMM — R12-proven structure; B producer now LDG.128.
// Tile 64x64x32, 256 threads, 8 warps (4m x 2n), warp tile m16n32.
// ============================================================
template<int N_, int K0_, int DIN_, int ACT_>
__global__ __launch_bounds__(256) void enc_gemm(
    const float* __restrict__ A0, int lda0,
    const float* __restrict__ A1, int lda1,
    const float* __restrict__ W, const float* __restrict__ bias,
    float* __restrict__ C, int ldc)
{
    constexpr int Ktot = DIN_;
    constexpr int NT   = (Ktot + BK - 1) / BK;
    __shared__ float As[2][64][36];
    __shared__ float Bs[2][32][72];

    const int tid  = threadIdx.x;
    const int lane = tid & 31;
    const int wid  = tid >> 5;
    const int wm16 = (wid >> 1) << 4;
    const int wn32 = (wid & 1) << 5;
    const int gid  = lane >> 2;
    const int tg   = lane & 3;

    const int bm_ = blockIdx.y * 64;
    const int bn_ = blockIdx.x * 64;

    const int amL = tid >> 3;
    const int akq = (tid & 7) << 2;
    const int bkL = tid >> 4;
    const int bnb = (tid & 15) << 2;

    float avv[2][4], bvv[2][4];

    auto ldgA = [&](int t) {
        const int kt = t * BK;
        #pragma unroll
        for (int half = 0; half < 2; half++) {
            const int m = bm_ + amL + half * 32;
            #pragma unroll
            for (int j = 0; j < 4; j++) {
                const int ig = kt + akq + j;
                float val = 0.f;
                if ((Ktot % BK == 0) || ig < Ktot)
                    val = (ig < K0_) ? __ldg(&A0[m * lda0 + ig])
                                     : __ldg(&A1[m * lda1 + (ig - K0_)]);
                avv[half][j] = val;
            }
        }
    };
    auto ldgB = [&](int t) {
        const int kt = t * BK;
        #pragma unroll
        for (int half = 0; half < 2; half++) {
            const int kg = kt + bkL + half * 16;
            const bool kok = (Ktot % BK == 0) || (kg < Ktot);
            if ((N_ % 64) == 0) {
                // W row stride N_ (mult of 64), bn_+bnb mult of 4 -> 16B aligned
                float4 v = make_float4(0.f, 0.f, 0.f, 0.f);
                if (kok)
                    v = __ldg(reinterpret_cast<const float4*>(
                            W + (size_t)kg * N_ + bn_ + bnb));
                bvv[half][0] = v.x; bvv[half][1] = v.y;
                bvv[half][2] = v.z; bvv[half][3] = v.w;
            } else {
                #pragma unroll
                for (int j = 0; j < 4; j++) {
                    const int n = bn_ + bnb + j;
                    float val = 0.f;
                    if (kok && n < N_)
                        val = __ldg(&W[(size_t)kg * N_ + n]);
                    bvv[half][j] = val;
                }
            }
        }
    };
    auto sts = [&](int buf) {
        #pragma unroll
        for (int half = 0; half < 2; half++) {
            const int mL = amL + half * 32;
            #pragma unroll
            for (int j = 0; j < 4; j++)
                As[buf][mL][akq + j] = tf32r(avv[half][j]);
        }
        #pragma unroll
        for (int half = 0; half < 2; half++) {
            const int kL = bkL + half * 16;
            #pragma unroll
            for (int j = 0; j < 4; j++)
                Bs[buf][kL][bnb + j] = tf32r(bvv[half][j]);
        }
    };

    float acc[4][4] = {};

    ldgA(0); ldgB(0);
    sts(0);
    __syncthreads();

    for (int t = 0; t < NT; t++) {
        const int cur = t & 1;
        const bool more = (t + 1 < NT);
        if (more) { ldgA(t + 1); ldgB(t + 1); }

        #pragma unroll
        for (int ks = 0; ks < 4; ks++) {
            const int kk = ks << 3;
            uint32_t a0 = __float_as_uint(As[cur][wm16 + gid    ][kk + tg    ]);
            uint32_t a1 = __float_as_uint(As[cur][wm16 + gid + 8][kk + tg    ]);
            uint32_t a2 = __float_as_uint(As[cur][wm16 + gid    ][kk + tg + 4]);
            uint32_t a3 = __float_as_uint(As[cur][wm16 + gid + 8][kk + tg + 4]);
            #pragma unroll
            for (int t4 = 0; t4 < 4; t4++) {
                const int col = wn32 + (t4 << 3) + gid;
                uint32_t b0 = __float_as_uint(Bs[cur][kk + tg    ][col]);
                uint32_t b1 = __float_as_uint(Bs[cur][kk + tg + 4][col]);
                asm volatile(
                    "mma.sync.aligned.m16n8k8.row.col.f32.tf32.tf32.f32 "
                    "{%0,%1,%2,%3}, {%4,%5,%6,%7}, {%8,%9}, {%0,%1,%2,%3};\n"
                    : "+f"(acc[t4][0]), "+f"(acc[t4][1]),
                      "+f"(acc[t4][2]), "+f"(acc[t4][3])
                    : "r"(a0), "r"(a1), "r"(a2), "r"(a3), "r"(b0), "r"(b1));
            }
        }
        if (more) sts(1 - cur);
        __syncthreads();
    }

    const int r0 = bm_ + wm16 + gid;
    const int r1 = r0 + 8;
    #pragma unroll
    for (int t = 0; t < 4; t++) {
        #pragma unroll
        for (int q = 0; q < 4; q++) {
            const int r  = (q < 2) ? r0 : r1;
            const int colL = wn32 + (t << 3) + (tg << 1) + (q & 1);
            const int cG = bn_ + colL;
            if ((N_ % 64) == 0 || cG < N_) {
                float v = acc[t][q] + __ldg(&bias[cG]);
                if (ACT_ == 1) v = elu1(v);
                C[r * ldc + cG] = v;
            }
        }
    }
}

// ============================================================
// mid2 — R12-passing structure; B producers in phases A/B now LDG.128.
// dual GEMM (mu|lv, K=523) + z + gate0 GEMM (K=299, z from smem zsm)
// + gate1 + gate2 + softmax. 64 rows/block, 256 thr, grid (1,64).
// ============================================================
__global__ __launch_bounds__(256) void mid2(
    const float* __restrict__ x,   const float* __restrict__ h2,
    const float* __restrict__ wmu, const float* __restrict__ bmu,
    const float* __restrict__ wlv, const float* __restrict__ blv,
    const float* __restrict__ epsv, const float* __restrict__ cc,
    const float* __restrict__ gw0, const float* __restrict__ gb0,
    const float* __restrict__ gw1, const float* __restrict__ gb1,
    const float* __restrict__ gw2, const float* __restrict__ gb2,
    float* __restrict__ mu_out, float* __restrict__ lv_out,
    float* __restrict__ q0, float* __restrict__ q1, float* __restrict__ q2,
    float* __restrict__ coeff)
{
    __shared__ float As[2][64][36];     // overlays: muS, g2s
    __shared__ float Bs[2][32][72];     // overlays: lvS, w1s
    __shared__ float g1s[64][65];
    __shared__ float zsm[64][33];

    const int tid  = threadIdx.x;
    const int lane = tid & 31;
    const int wid  = tid >> 5;
    const int wm16 = (wid >> 1) << 4;
    const int wn32 = (wid & 1) << 5;
    const int gid  = lane >> 2;
    const int tg   = lane & 3;

    const int bm_ = blockIdx.y * 64;

    const int amL = tid >> 3;
    const int akq = (tid & 7) << 2;
    const int bkL = tid >> 4;
    const int bnb = (tid & 15) << 2;

    const int r0 = bm_ + wm16 + gid;
    const int r1 = r0 + 8;

    float avv[2][4], bvv[2][4];

    auto sts = [&](int buf) {
        #pragma unroll
        for (int half = 0; half < 2; half++) {
            const int mL = amL + half * 32;
            #pragma unroll
            for (int j = 0; j < 4; j++)
                As[buf][mL][akq + j] = tf32r(avv[half][j]);
        }
        #pragma unroll
        for (int half = 0; half < 2; half++) {
            const int kL = bkL + half * 16;
            #pragma unroll
            for (int j = 0; j < 4; j++)
                Bs[buf][kL][bnb + j] = tf32r(bvv[half][j]);
        }
    };

    // Phase A: dual GEMM mu|lv, K=523
    {
        constexpr int Ktot = FRAME + HIDDEN;
        constexpr int NT   = (Ktot + BK - 1) / BK;

        auto ldgA = [&](int t) {
            const int kt = t * BK;
            #pragma unroll
            for (int half = 0; half < 2; half++) {
                const int m = bm_ + amL + half * 32;
                #pragma unroll
                for (int j = 0; j < 4; j++) {
                    const int ig = kt + akq + j;
                    float val = 0.f;
                    if (ig < Ktot)
                        val = (ig < FRAME) ? __ldg(&x[m * FRAME + ig])
                                           : __ldg(&h2[m * HIDDEN + (ig - FRAME)]);
                    avv[half][j] = val;
                }
            }
        };
        auto ldgB = [&](int t) {
            const int kt = t * BK;
            #pragma unroll
            for (int half = 0; half < 2; half++) {
                const int kg = kt + bkL + half * 16;
                const bool kok = kg < Ktot;
                // bnb in {0..60} mult of 4; each 4-group lies wholly in
                // wmu (bnb<32) or wlv (bnb>=32); rows are 32 floats -> aligned.
                const float* base = (bnb < 32) ? (wmu + kg * 32 + bnb)
                                               : (wlv + kg * 32 + (bnb - 32));
                float4 v = make_float4(0.f, 0.f, 0.f, 0.f);
                if (kok) v = __ldg(reinterpret_cast<const float4*>(base));
                bvv[half][0] = v.x; bvv[half][1] = v.y;
                bvv[half][2] = v.z; bvv[half][3] = v.w;
            }
        };

        float acc[4][4] = {};
        ldgA(0); ldgB(0);
        sts(0);
        __syncthreads();

        for (int t = 0; t < NT; t++) {
            const int cur = t & 1;
            const bool more = (t + 1 < NT);
            if (more) { ldgA(t + 1); ldgB(t + 1); }

            #pragma unroll
            for (int ks = 0; ks < 4; ks++) {
                const int kk = ks << 3;
                uint32_t a0 = __float_as_uint(As[cur][wm16 + gid    ][kk + tg    ]);
                uint32_t a1 = __float_as_uint(As[cur][wm16 + gid + 8][kk + tg    ]);
                uint32_t a2 = __float_as_uint(As[cur][wm16 + gid    ][kk + tg + 4]);
                uint32_t a3 = __float_as_uint(As[cur][wm16 + gid + 8][kk + tg + 4]);
                #pragma unroll
                for (int t4 = 0; t4 < 4; t4++) {
                    const int col = wn32 + (t4 << 3) + gid;
                    uint32_t b0 = __float_as_uint(Bs[cur][kk + tg    ][col]);
                    uint32_t b1 = __float_as_uint(Bs[cur][kk + tg + 4][col]);
                    asm volatile(
                        "mma.sync.aligned.m16n8k8.row.col.f32.tf32.tf32.f32 "
                        "{%0,%1,%2,%3}, {%4,%5,%6,%7}, {%8,%9}, {%0,%1,%2,%3};\n"
                        : "+f"(acc[t4][0]), "+f"(acc[t4][1]),
                          "+f"(acc[t4][2]), "+f"(acc[t4][3])
                        : "r"(a0), "r"(a1), "r"(a2), "r"(a3), "r"(b0), "r"(b1));
                }
            }
            if (more) sts(1 - cur);
            __syncthreads();
        }

        float* muS = &As[0][0][0];
        float* lvS = &Bs[0][0][0];

        #pragma unroll
        for (int t = 0; t < 4; t++) {
            #pragma unroll
            for (int q = 0; q < 4; q++) {
                const int r  = (q < 2) ? r0 : r1;
                const int rL = r - bm_;
                const int colL = wn32 + (t << 3) + (tg << 1) + (q & 1);
                if (colL < 32) {
                    const float m_ = acc[t][q] + __ldg(&bmu[colL]);
                    mu_out[r * 32 + colL] = m_;
                    muS[rL * 33 + colL] = m_;
                } else {
                    const int cl = colL - 32;
                    const float l_ = acc[t][q] + __ldg(&blv[cl]);
                    lv_out[r * 32 + cl] = l_;
                    lvS[rL * 33 + cl] = l_;
                }
            }
        }
        __syncthreads();

        for (int e = tid; e < 64 * 32; e += 256) {
            const int rL = e >> 5, cl = e & 31;
            const int r = bm_ + rL;
            const float zv = fmaf(__ldg(&epsv[r * 32 + cl]),
                                  expf(0.5f * lvS[rL * 33 + cl]), muS[rL * 33 + cl]);
            zsm[rL][cl] = zv;
            q0[r * 320 + cl] = zv;
            q1[r * 288 + cl] = zv;
            q2[r * 288 + cl] = zv;
        }
        __syncthreads();
    }

    // Phase B: gate0 GEMM, K=299, N=64
    {
        constexpr int Ktot = IN0;
        constexpr int NT   = (Ktot + BK - 1) / BK;

        auto ldgA = [&](int t) {
            const int kt = t * BK;
            #pragma unroll
            for (int half = 0; half < 2; half++) {
                const int mL = amL + half * 32;
                const int m  = bm_ + mL;
                #pragma unroll
                for (int j = 0; j < 4; j++) {
                    const int ig = kt + akq + j;
                    float val = 0.f;
                    if (ig < 32)            val = zsm[mL][ig];
                    else if (ig < Ktot)     val = __ldg(&cc[m * FRAME + (ig - 32)]);
                    avv[half][j] = val;
                }
            }
        };
        auto ldgB = [&](int t) {
            const int kt = t * BK;
            #pragma unroll
            for (int half = 0; half < 2; half++) {
                const int kg = kt + bkL + half * 16;
                const bool kok = kg < Ktot;
                // gw0 rows are 64 floats; bnb mult of 4 -> aligned float4
                float4 v = make_float4(0.f, 0.f, 0.f, 0.f);
                if (kok)
                    v = __ldg(reinterpret_cast<const float4*>(gw0 + kg * 64 + bnb));
                bvv[half][0] = v.x; bvv[half][1] = v.y;
                bvv[half][2] = v.z; bvv[half][3] = v.w;
            }
        };

        float acc[4][4] = {};
        ldgA(0); ldgB(0);
        sts(0);
        __syncthreads();

        for (int t = 0; t < NT; t++) {
            const int cur = t & 1;
            const bool more = (t + 1 < NT);
            if (more) { ldgA(t + 1); ldgB(t + 1); }

            #pragma unroll
            for (int ks = 0; ks < 4; ks++) {
                const int kk = ks << 3;
                uint32_t a0 = __float_as_uint(As[cur][wm16 + gid    ][kk + tg    ]);
                uint32_t a1 = __float_as_uint(As[cur][wm16 + gid + 8][kk + tg    ]);
                uint32_t a2 = __float_as_uint(As[cur][wm16 + gid    ][kk + tg + 4]);
                uint32_t a3 = __float_as_uint(As[cur][wm16 + gid + 8][kk + tg + 4]);
                #pragma unroll
                for (int t4 = 0; t4 < 4; t4++) {
                    const int col = wn32 + (t4 << 3) + gid;
                    uint32_t b0 = __float_as_uint(Bs[cur][kk + tg    ][col]);
                    uint32_t b1 = __float_as_uint(Bs[cur][kk + tg + 4][col]);
                    asm volatile(
                        "mma.sync.aligned.m16n8k8.row.col.f32.tf32.tf32.f32 "
                        "{%0,%1,%2,%3}, {%4,%5,%6,%7}, {%8,%9}, {%0,%1,%2,%3};\n"
                        : "+f"(acc[t4][0]), "+f"(acc[t4][1]),
                          "+f"(acc[t4][2]), "+f"(acc[t4][3])
                        : "r"(a0), "r"(a1), "r"(a2), "r"(a3), "r"(b0), "r"(b1));
                }
            }
            if (more) sts(1 - cur);
            __syncthreads();
        }

        #pragma unroll
        for (int t = 0; t < 4; t++) {
            #pragma unroll
            for (int q = 0; q < 4; q++) {
                const int rL = ((q < 2) ? r0 : r1) - bm_;
                const int colL = wn32 + (t << 3) + (tg << 1) + (q & 1);
                g1s[rL][colL] = elu1(acc[t][q] + __ldg(&gb0[colL]));
            }
        }
        __syncthreads();
    }

    // Phase C: gate1 (64x64), w1 overlay on Bs
    {
        float* w1f = &Bs[0][0][0];
        for (int i = tid; i < 64 * 64; i += 256)
            w1f[(i >> 6) * 72 + (i & 63)] = __ldg(&gw1[i]);
        __syncthreads();

        float* g2f = &As[0][0][0];
        const int row = tid >> 2;
        const int cs  = tid & 3;
        float a16[16];
        #pragma unroll
        for (int j = 0; j < 16; j++) a16[j] = __ldg(&gb1[cs + (j << 2)]);
        #pragma unroll
        for (int k = 0; k < 64; k++) {
            const float gv = g1s[row][k];
            #pragma unroll
            for (int j = 0; j < 16; j++)
                a16[j] = fmaf(gv, w1f[k * 72 + cs + (j << 2)], a16[j]);
        }
        #pragma unroll
        for (int j = 0; j < 16; j++)
            g2f[row * 65 + cs + (j << 2)] = elu1(a16[j]);
        __syncthreads();
    }

    // Phase D: gate2 + softmax -> coeff
    if (tid < 64) {
        const float* g2f = &As[0][0][0];
        float lg[EXPERTS];
        #pragma unroll
        for (int e = 0; e < EXPERTS; e++) lg[e] = __ldg(&gb2[e]);
        #pragma unroll
        for (int k = 0; k < 64; k++) {
            const float gv = g2f[tid * 65 + k];
            #pragma unroll
            for (int e = 0; e < EXPERTS; e++)
                lg[e] = fmaf(gv, __ldg(&gw2[k * EXPERTS + e]), lg[e]);
        }
        float mx = lg[0];
        #pragma unroll
        for (int e = 1; e < EXPERTS; e++) mx = fmaxf(mx, lg[e]);
        float s = 0.f;
        #pragma unroll
        for (int e = 0; e < EXPERTS; e++) { lg[e] = expf(lg[e] - mx); s += lg[e]; }
        const float inv = 1.f / s;
        #pragma unroll
        for (int e = 0; e < EXPERTS; e++)
            coeff[(bm_ + tid) * EXPERTS + e] = lg[e] * inv;
    }
}

// ============================================================
// Decoder GEMM — R12-proven (verbatim): packed A, double-buffered.
// ============================================================
template<int N_, int DINR_, int DINP_, int LDA_, int ACT_>
__global__ __launch_bounds__(256) void dec_gemm(
    const float* __restrict__ A,
    const float* __restrict__ coeff,
    const float* __restrict__ W, const float* __restrict__ bias,
    float* __restrict__ C, int ldc)
{
    constexpr int E_  = EXPERTS;
    constexpr int TPE = DINP_ / 32;
    constexpr int NT  = E_ * TPE;
    __shared__ __align__(16) float As[2][64][36];
    __shared__ __align__(16) float Bs[2][32][72];

    const int tid  = threadIdx.x;
    const int lane = tid & 31;
    const int wid  = tid >> 5;
    const int wm16 = (wid >> 1) << 4;
    const int wn32 = (wid & 1) << 5;
    const int gid  = lane >> 2;
    const int tg   = lane & 3;

    const int bm_ = blockIdx.y * 64;
    const int bn_ = blockIdx.x * 64;

    const int amL = tid >> 3;
    const int akq = (tid & 7) << 2;
    const int bkL = tid >> 4;
    const int bnb = (tid & 15) << 2;

    const float* Ar0  = A + (bm_ + amL) * LDA_;
    const float* Ar1  = Ar0 + 32 * LDA_;
    const float* cf0p = coeff + (bm_ + amL) * E_;
    const float* cf1p = cf0p + 32 * E_;

    float avv[2][4], bvv[2][4];

    auto ldgA = [&](int t) {
        const int e  = t / TPE;
        const int i0 = (t - e * TPE) * 32 + akq;
        const float c0 = __ldg(&cf0p[e]);
        const float c1 = __ldg(&cf1p[e]);
        const float4 v0 = __ldg(reinterpret_cast<const float4*>(Ar0 + i0));
        const float4 v1 = __ldg(reinterpret_cast<const float4*>(Ar1 + i0));
        avv[0][0] = v0.x * c0; avv[0][1] = v0.y * c0; avv[0][2] = v0.z * c0; avv[0][3] = v0.w * c0;
        avv[1][0] = v1.x * c1; avv[1][1] = v1.y * c1; avv[1][2] = v1.z * c1; avv[1][3] = v1.w * c1;
    };
    auto ldgB = [&](int t) {
        const int e  = t / TPE;
        const int k0 = (t - e * TPE) * 32;
        const float* We = W + (size_t)e * DINR_ * N_;
        #pragma unroll
        for (int half = 0; half < 2; half++) {
            const int kl = k0 + bkL + half * 16;
            const bool kok = (DINR_ == DINP_) || (kl < DINR_);
            if ((N_ % 64) == 0) {
                float4 v = make_float4(0.f, 0.f, 0.f, 0.f);
                if (kok)
                    v = __ldg(reinterpret_cast<const float4*>(We + (size_t)kl * N_ + bn_ + bnb));
                bvv[half][0] = v.x; bvv[half][1] = v.y; bvv[half][2] = v.z; bvv[half][3] = v.w;
            } else {
                #pragma unroll
                for (int j = 0; j < 4; j++) {
                    const int n = bn_ + bnb + j;
                    float v = 0.f;
                    if (kok && n < N_) v = __ldg(&We[(size_t)kl * N_ + n]);
                    bvv[half][j] = v;
                }
            }
        }
    };
    auto sts = [&](int buf) {
        #pragma unroll
        for (int half = 0; half < 2; half++) {
            const float4 t4 = make_float4(tf32r(avv[half][0]), tf32r(avv[half][1]),
                                          tf32r(avv[half][2]), tf32r(avv[half][3]));
            *reinterpret_cast<float4*>(&As[buf][amL + half * 32][akq]) = t4;
        }
        #pragma unroll
        for (int half = 0; half < 2; half++) {
            const float4 t4 = make_float4(tf32r(bvv[half][0]), tf32r(bvv[half][1]),
                                          tf32r(bvv[half][2]), tf32r(bvv[half][3]));
            *reinterpret_cast<float4*>(&Bs[buf][bkL + half * 16][bnb]) = t4;
        }
    };

    float acc[4][4] = {};

    ldgA(0); ldgB(0);
    sts(0);
    __syncthreads();

    for (int t = 0; t < NT; t++) {
        const int cur = t & 1;
        const bool more = (t + 1 < NT);
        if (more) { ldgA(t + 1); ldgB(t + 1); }

        #pragma unroll
        for (int ks = 0; ks < 4; ks++) {
            const int kk = ks << 3;
            uint32_t a0 = __float_as_uint(As[cur][wm16 + gid    ][kk + tg    ]);
            uint32_t a1 = __float_as_uint(As[cur][wm16 + gid + 8][kk + tg    ]);
            uint32_t a2 = __float_as_uint(As[cur][wm16 + gid    ][kk + tg + 4]);
            uint32_t a3 = __float_as_uint(As[cur][wm16 + gid + 8][kk + tg + 4]);
            #pragma unroll
            for (int t4i = 0; t4i < 4; t4i++) {
                const int col = wn32 + (t4i << 3) + gid;
                uint32_t b0 = __float_as_uint(Bs[cur][kk + tg    ][col]);
                uint32_t b1 = __float_as_uint(Bs[cur][kk + tg + 4][col]);
                asm volatile(
                    "mma.sync.aligned.m16n8k8.row.col.f32.tf32.tf32.f32 "
                    "{%0,%1,%2,%3}, {%4,%5,%6,%7}, {%8,%9}, {%0,%1,%2,%3};\n"
                    : "+f"(acc[t4i][0]), "+f"(acc[t4i][1]),
                      "+f"(acc[t4i][2]), "+f"(acc[t4i][3])
                    : "r"(a0), "r"(a1), "r"(a2), "r"(a3), "r"(b0), "r"(b1));
            }
        }
        if (more) sts(1 - cur);
        __syncthreads();
    }

    const int r0 = bm_ + wm16 + gid;
    const int r1 = r0 + 8;
    float cf0[E_], cf1[E_];
    #pragma unroll
    for (int e = 0; e < E_; e++) {
        cf0[e] = coeff[r0 * E_ + e];
        cf1[e] = coeff[r1 * E_ + e];
    }

    #pragma unroll
    for (int t = 0; t < 4; t++) {
        #pragma unroll
        for (int q = 0; q < 4; q++) {
            const int r  = (q < 2) ? r0 : r1;
            const int colL = wn32 + (t << 3) + (tg << 1) + (q & 1);
            const int cG = bn_ + colL;
            if ((N_ % 64) == 0 || cG < N_) {
                const float* cf = (q < 2) ? cf0 : cf1;
                float bb = 0.f;
                #pragma unroll
                for (int e = 0; e < E_; e++)
                    bb = fmaf(cf[e], __ldg(&bias[e * N_ + cG]), bb);
                float v = acc[t][q] + bb;
                if (ACT_ == 1) v = elu1(v);
                C[r * ldc + cG] = v;
            }
        }
    }
}

// ---------------- pack kernel: c -> q0 cols [32, 320) ----------------
__global__ void pack_c(const float* __restrict__ c, float* __restrict__ q0)
{
    int idx = blockIdx.x * blockDim.x + threadIdx.x;
    if (idx >= BATCH * 288) return;
    const int r = idx / 288;
    const int col = 32 + idx % 288;     // 32..319
    q0[r * 320 + col] = (col < IN0) ? c[r * FRAME + (col - 32)] : 0.f;
}

// ---------------- launch ----------------
extern "C" void kernel_launch(void* const* d_in, const int* in_sizes, int n_in,
                              void* d_out, int out_size)
{
    const float* x       = (const float*)d_in[0];
    const float* c       = (const float*)d_in[1];
    const float* eps     = (const float*)d_in[2];
    const float* enc_w1  = (const float*)d_in[3];
    const float* enc_b1  = (const float*)d_in[4];
    const float* enc_w2  = (const float*)d_in[5];
    const float* enc_b2  = (const float*)d_in[6];
    const float* enc_wmu = (const float*)d_in[7];
    const float* enc_bmu = (const float*)d_in[8];
    const float* enc_wlv = (const float*)d_in[9];
    const float* enc_blv = (const float*)d_in[10];
    const float* gw0     = (const float*)d_in[11];
    const float* gb0     = (const float*)d_in[12];
    const float* gw1     = (const float*)d_in[13];
    const float* gb1     = (const float*)d_in[14];
    const float* gw2     = (const float*)d_in[15];
    const float* gb2     = (const float*)d_in[16];
    const float* w0      = (const float*)d_in[17];
    const float* b0      = (const float*)d_in[18];
    const float* w1      = (const float*)d_in[19];
    const float* b1      = (const float*)d_in[20];
    const float* w2      = (const float*)d_in[21];
    const float* b2      = (const float*)d_in[22];
    float* out = (float*)d_out;

    float *h1, *h2, *coef, *q0, *q1, *q2;
    cudaGetSymbolAddress((void**)&h1,   g_h1);
    cudaGetSymbolAddress((void**)&h2,   g_h2);
    cudaGetSymbolAddress((void**)&coef, g_coef);
    cudaGetSymbolAddress((void**)&q0,   g_q0);
    cudaGetSymbolAddress((void**)&q1,   g_q1);
    cudaGetSymbolAddress((void**)&q2,   g_q2);

    const dim3 blk(256);
    const dim3 gridH(HIDDEN / 64, BATCH / 64);              // (4, 64)
    const dim3 grid1(1, BATCH / 64);                        // (1, 64)
    const dim3 gridO((OUTD + 63) / 64, BATCH / 64);         // (5, 64)

    // pack c into q0 cols [32,320)
    pack_c<<<(BATCH * 288 + 255) / 256, 256>>>(c, q0);
    // encoder layer 1: h1 = elu([x, c] @ enc_w1 + b1)   K=534
    enc_gemm<HIDDEN, FRAME, 2*FRAME, 1><<<gridH, blk>>>(
        x, FRAME, c, FRAME, enc_w1, enc_b1, h1, HIDDEN);
    // encoder layer 2: h2 = elu([x, h1] @ enc_w2 + b2)  K=523
    enc_gemm<HIDDEN, FRAME, FRAME+HIDDEN, 1><<<gridH, blk>>>(
        x, FRAME, h1, HIDDEN, enc_w2, enc_b2, h2, HIDDEN);
    // mid2: mu/lv + z + gate0 + gate1 + gate2 + softmax (one launch)
    mid2<<<grid1, blk>>>(
        x, h2, enc_wmu, enc_bmu, enc_wlv, enc_blv, eps, c,
        gw0, gb0, gw1, gb1, gw2, gb2,
        out + OFF_MU, out + OFF_LV, q0, q1, q2, coef);
    // MoE decoder layer 0: DIN 299 (pad 320) -> d1 into q1 cols [32,288)
    dec_gemm<HIDDEN, IN0, 320, 320, 1><<<gridH, blk>>>(
        q0, coef, w0, b0, q1 + 32, IN1);
    // MoE decoder layer 1: DIN 288 exact -> d2 into q2 cols [32,288)
    dec_gemm<HIDDEN, IN1, 288, 288, 1><<<gridH, blk>>>(
        q1, coef, w1, b1, q2 + 32, IN1);
    // MoE decoder layer 2 (no act): N=267 -> output
    dec_gemm<OUTD, IN1, 288, 288, 0><<<gridO, blk>>>(
        q2, coef, w2, b2, out, OUTD);
}

// round 16
// speedup vs baseline: 1.4544x; 1.0226x over previous
#include <cuda_runtime.h>
#include <cstdint>

// ---------------- problem constants ----------------
#define BATCH   4096
#define FRAME   267
#define LATENT  32
#define HIDDEN  256
#define GATE_H  64
#define EXPERTS 6
#define IN0     (LATENT + FRAME)    // 299
#define IN1     (LATENT + HIDDEN)   // 288
#define OUTD    FRAME               // 267

#define OFF_MU  (BATCH * OUTD)
#define OFF_LV  (OFF_MU + BATCH * LATENT)

// ---------------- scratch (allocation-free) ----------------
__device__ float g_coef[BATCH * EXPERTS];
// packed, 16B-aligned input rows (544 = 34*16 bytes-stride/4)
__device__ __align__(16) float g_xc [BATCH * 544];  // [x | c | 0pad]
__device__ __align__(16) float g_xh [BATCH * 544];  // [x | h1 | 0pad]
__device__ __align__(16) float g_xh2[BATCH * 544];  // [x | h2 | 0pad]
// packed decoder inputs
__device__ __align__(16) float g_q0[BATCH * 320];   // [z | c | 0pad]
__device__ __align__(16) float g_q1[BATCH * 288];   // [z | d1]
__device__ __align__(16) float g_q2[BATCH * 288];   // [z | d2]

__device__ __forceinline__ float elu1(float x) { return x > 0.f ? x : expm1f(x); }

__device__ __forceinline__ float tf32r(float x) {
    float y;
    asm("cvt.rna.tf32.f32 %0, %1;" : "=f"(y) : "f"(x));
    return y;
}

#define BK 32

// ============================================================
// Unified packed GEMM (generalizes the R15 dec_gemm, proven):
//   C[m,n] = act( sum_e cf[m,e] * (A[m, e-local] @ W_e) + biasblend )
// A rows packed/aligned, DINP_ = per-expert K padded to mult of 32;
// B rows kl >= DINR_ zero-guarded so A pad content is annihilated.
// E_=1: coeff fold and blended bias compiled out.
// Tile 64x64x32, 256 threads, 8 warps (4m x 2n), double-buffered.
// ============================================================
template<int N_, int DINR_, int DINP_, int LDA_, int E_, int ACT_>
__global__ __launch_bounds__(256) void gemm_p(
    const float* __restrict__ A,
    const float* __restrict__ coeff,
    const float* __restrict__ W, const float* __restrict__ bias,
    float* __restrict__ C, int ldc)
{
    constexpr int TPE = DINP_ / 32;
    constexpr int NT  = E_ * TPE;
    __shared__ __align__(16) float As[2][64][36];
    __shared__ __align__(16) float Bs[2][32][72];

    const int tid  = threadIdx.x;
    const int lane = tid & 31;
    const int wid  = tid >> 5;
    const int wm16 = (wid >> 1) << 4;
    const int wn32 = (wid & 1) << 5;
    const int gid  = lane >> 2;
    const int tg   = lane & 3;

    const int bm_ = blockIdx.y * 64;
    const int bn_ = blockIdx.x * 64;

    const int amL = tid >> 3;
    const int akq = (tid & 7) << 2;
    const int bkL = tid >> 4;
    const int bnb = (tid & 15) << 2;

    const float* Ar0  = A + (size_t)(bm_ + amL) * LDA_;
    const float* Ar1  = Ar0 + (size_t)32 * LDA_;
    const float* cf0p = (E_ > 1) ? coeff + (bm_ + amL) * E_ : nullptr;
    const float* cf1p = (E_ > 1) ? cf0p + 32 * E_ : nullptr;

    float avv[2][4], bvv[2][4];

    auto ldgA = [&](int t) {
        const int e  = (E_ > 1) ? (t / TPE) : 0;
        const int i0 = (t - e * TPE) * 32 + akq;
        const float4 v0 = __ldg(reinterpret_cast<const float4*>(Ar0 + i0));
        const float4 v1 = __ldg(reinterpret_cast<const float4*>(Ar1 + i0));
        if (E_ > 1) {
            const float c0 = __ldg(&cf0p[e]);
            const float c1 = __ldg(&cf1p[e]);
            avv[0][0] = v0.x * c0; avv[0][1] = v0.y * c0;
            avv[0][2] = v0.z * c0; avv[0][3] = v0.w * c0;
            avv[1][0] = v1.x * c1; avv[1][1] = v1.y * c1;
            avv[1][2] = v1.z * c1; avv[1][3] = v1.w * c1;
        } else {
            avv[0][0] = v0.x; avv[0][1] = v0.y; avv[0][2] = v0.z; avv[0][3] = v0.w;
            avv[1][0] = v1.x; avv[1][1] = v1.y; avv[1][2] = v1.z; avv[1][3] = v1.w;
        }
    };
    auto ldgB = [&](int t) {
        const int e  = (E_ > 1) ? (t / TPE) : 0;
        const int k0 = (t - e * TPE) * 32;
        const float* We = W + (size_t)e * DINR_ * N_;
        #pragma unroll
        for (int half = 0; half < 2; half++) {
            const int kl = k0 + bkL + half * 16;
            const bool kok = (DINR_ == DINP_) || (kl < DINR_);
            if ((N_ % 64) == 0) {
                float4 v = make_float4(0.f, 0.f, 0.f, 0.f);
                if (kok)
                    v = __ldg(reinterpret_cast<const float4*>(We + (size_t)kl * N_ + bn_ + bnb));
                bvv[half][0] = v.x; bvv[half][1] = v.y; bvv[half][2] = v.z; bvv[half][3] = v.w;
            } else {
                #pragma unroll
                for (int j = 0; j < 4; j++) {
                    const int n = bn_ + bnb + j;
                    float v = 0.f;
                    if (kok && n < N_) v = __ldg(&We[(size_t)kl * N_ + n]);
                    bvv[half][j] = v;
                }
            }
        }
    };
    auto sts = [&](int buf) {
        #pragma unroll
        for (int half = 0; half < 2; half++) {
            const float4 t4 = make_float4(tf32r(avv[half][0]), tf32r(avv[half][1]),
                                          tf32r(avv[half][2]), tf32r(avv[half][3]));
            *reinterpret_cast<float4*>(&As[buf][amL + half * 32][akq]) = t4;
        }
        #pragma unroll
        for (int half = 0; half < 2; half++) {
            const float4 t4 = make_float4(tf32r(bvv[half][0]), tf32r(bvv[half][1]),
                                          tf32r(bvv[half][2]), tf32r(bvv[half][3]));
            *reinterpret_cast<float4*>(&Bs[buf][bkL + half * 16][bnb]) = t4;
        }
    };

    float acc[4][4] = {};

    ldgA(0); ldgB(0);
    sts(0);
    __syncthreads();

    for (int t = 0; t < NT; t++) {
        const int cur = t & 1;
        const bool more = (t + 1 < NT);
        if (more) { ldgA(t + 1); ldgB(t + 1); }

        #pragma unroll
        for (int ks = 0; ks < 4; ks++) {
            const int kk = ks << 3;
            uint32_t a0 = __float_as_uint(As[cur][wm16 + gid    ][kk + tg    ]);
            uint32_t a1 = __float_as_uint(As[cur][wm16 + gid + 8][kk + tg    ]);
            uint32_t a2 = __float_as_uint(As[cur][wm16 + gid    ][kk + tg + 4]);
            uint32_t a3 = __float_as_uint(As[cur][wm16 + gid + 8][kk + tg + 4]);
            #pragma unroll
            for (int t4i = 0; t4i < 4; t4i++) {
                const int col = wn32 + (t4i << 3) + gid;
                uint32_t b0 = __float_as_uint(Bs[cur][kk + tg    ][col]);
                uint32_t b1 = __float_as_uint(Bs[cur][kk + tg + 4][col]);
                asm volatile(
                    "mma.sync.aligned.m16n8k8.row.col.f32.tf32.tf32.f32 "
                    "{%0,%1,%2,%3}, {%4,%5,%6,%7}, {%8,%9}, {%0,%1,%2,%3};\n"
                    : "+f"(acc[t4i][0]), "+f"(acc[t4i][1]),
                      "+f"(acc[t4i][2]), "+f"(acc[t4i][3])
                    : "r"(a0), "r"(a1), "r"(a2), "r"(a3), "r"(b0), "r"(b1));
            }
        }
        if (more) sts(1 - cur);
        __syncthreads();
    }

    const int r0 = bm_ + wm16 + gid;
    const int r1 = r0 + 8;
    float cf0[E_], cf1[E_];
    if (E_ > 1) {
        #pragma unroll
        for (int e = 0; e < E_; e++) {
            cf0[e] = coeff[r0 * E_ + e];
            cf1[e] = coeff[r1 * E_ + e];
        }
    }

    #pragma unroll
    for (int t = 0; t < 4; t++) {
        #pragma unroll
        for (int q = 0; q < 4; q++) {
            const int r  = (q < 2) ? r0 : r1;
            const int colL = wn32 + (t << 3) + (tg << 1) + (q & 1);
            const int cG = bn_ + colL;
            if ((N_ % 64) == 0 || cG < N_) {
                float bb;
                if (E_ > 1) {
                    const float* cf = (q < 2) ? cf0 : cf1;
                    bb = 0.f;
                    #pragma unroll
                    for (int e = 0; e < E_; e++)
                        bb = fmaf(cf[e], __ldg(&bias[e * N_ + cG]), bb);
                } else {
                    bb = __ldg(&bias[cG]);
                }
                float v = acc[t][q] + bb;
                if (ACT_ == 1) v = elu1(v);
                C[(size_t)r * ldc + cG] = v;
            }
        }
    }
}

// ============================================================
// mid2 — R15-passing structure; phase A now reads packed xh2 rows
// with unguarded LDG.128 (K padded 523->544, B rows >=523 zeroed).
// dual GEMM (mu|lv) + z + gate0 (z from zsm, c from input) + gate1
// + gate2 + softmax. 64 rows/block, 256 thr, grid (1,64).
// ============================================================
__global__ __launch_bounds__(256) void mid2(
    const float* __restrict__ xh2,
    const float* __restrict__ wmu, const float* __restrict__ bmu,
    const float* __restrict__ wlv, const float* __restrict__ blv,
    const float* __restrict__ epsv, const float* __restrict__ cc,
    const float* __restrict__ gw0, const float* __restrict__ gb0,
    const float* __restrict__ gw1, const float* __restrict__ gb1,
    const float* __restrict__ gw2, const float* __restrict__ gb2,
    float* __restrict__ mu_out, float* __restrict__ lv_out,
    float* __restrict__ q0, float* __restrict__ q1, float* __restrict__ q2,
    float* __restrict__ coeff)
{
    __shared__ float As[2][64][36];     // overlays: muS, g2s
    __shared__ float Bs[2][32][72];     // overlays: lvS, w1s
    __shared__ float g1s[64][65];
    __shared__ float zsm[64][33];

    const int tid  = threadIdx.x;
    const int lane = tid & 31;
    const int wid  = tid >> 5;
    const int wm16 = (wid >> 1) << 4;
    const int wn32 = (wid & 1) << 5;
    const int gid  = lane >> 2;
    const int tg   = lane & 3;

    const int bm_ = blockIdx.y * 64;

    const int amL = tid >> 3;
    const int akq = (tid & 7) << 2;
    const int bkL = tid >> 4;
    const int bnb = (tid & 15) << 2;

    const int r0 = bm_ + wm16 + gid;
    const int r1 = r0 + 8;

    float avv[2][4], bvv[2][4];

    auto sts = [&](int buf) {
        #pragma unroll
        for (int half = 0; half < 2; half++) {
            const int mL = amL + half * 32;
            #pragma unroll
            for (int j = 0; j < 4; j++)
                As[buf][mL][akq + j] = tf32r(avv[half][j]);
        }
        #pragma unroll
        for (int half = 0; half < 2; half++) {
            const int kL = bkL + half * 16;
            #pragma unroll
            for (int j = 0; j < 4; j++)
                Bs[buf][kL][bnb + j] = tf32r(bvv[half][j]);
        }
    };

    // Phase A: dual GEMM mu|lv, K=523 (padded 544)
    {
        constexpr int Ktot = FRAME + HIDDEN;   // 523
        constexpr int NT   = 544 / BK;         // 17

        const float* Ar0 = xh2 + (size_t)(bm_ + amL) * 544;
        const float* Ar1 = Ar0 + (size_t)32 * 544;

        auto ldgA = [&](int t) {
            const int i0 = t * BK + akq;
            const float4 v0 = __ldg(reinterpret_cast<const float4*>(Ar0 + i0));
            const float4 v1 = __ldg(reinterpret_cast<const float4*>(Ar1 + i0));
            avv[0][0] = v0.x; avv[0][1] = v0.y; avv[0][2] = v0.z; avv[0][3] = v0.w;
            avv[1][0] = v1.x; avv[1][1] = v1.y; avv[1][2] = v1.z; avv[1][3] = v1.w;
        };
        auto ldgB = [&](int t) {
            const int kt = t * BK;
            #pragma unroll
            for (int half = 0; half < 2; half++) {
                const int kg = kt + bkL + half * 16;
                const bool kok = kg < Ktot;
                const float* base = (bnb < 32) ? (wmu + kg * 32 + bnb)
                                               : (wlv + kg * 32 + (bnb - 32));
                float4 v = make_float4(0.f, 0.f, 0.f, 0.f);
                if (kok) v = __ldg(reinterpret_cast<const float4*>(base));
                bvv[half][0] = v.x; bvv[half][1] = v.y;
                bvv[half][2] = v.z; bvv[half][3] = v.w;
            }
        };

        float acc[4][4] = {};
        ldgA(0); ldgB(0);
        sts(0);
        __syncthreads();

        for (int t = 0; t < NT; t++) {
            const int cur = t & 1;
            const bool more = (t + 1 < NT);
            if (more) { ldgA(t + 1); ldgB(t + 1); }

            #pragma unroll
            for (int ks = 0; ks < 4; ks++) {
                const int kk = ks << 3;
                uint32_t a0 = __float_as_uint(As[cur][wm16 + gid    ][kk + tg    ]);
                uint32_t a1 = __float_as_uint(As[cur][wm16 + gid + 8][kk + tg    ]);
                uint32_t a2 = __float_as_uint(As[cur][wm16 + gid    ][kk + tg + 4]);
                uint32_t a3 = __float_as_uint(As[cur][wm16 + gid + 8][kk + tg + 4]);
                #pragma unroll
                for (int t4 = 0; t4 < 4; t4++) {
                    const int col = wn32 + (t4 << 3) + gid;
                    uint32_t b0 = __float_as_uint(Bs[cur][kk + tg    ][col]);
                    uint32_t b1 = __float_as_uint(Bs[cur][kk + tg + 4][col]);
                    asm volatile(
                        "mma.sync.aligned.m16n8k8.row.col.f32.tf32.tf32.f32 "
                        "{%0,%1,%2,%3}, {%4,%5,%6,%7}, {%8,%9}, {%0,%1,%2,%3};\n"
                        : "+f"(acc[t4][0]), "+f"(acc[t4][1]),
                          "+f"(acc[t4][2]), "+f"(acc[t4][3])
                        : "r"(a0), "r"(a1), "r"(a2), "r"(a3), "r"(b0), "r"(b1));
                }
            }
            if (more) sts(1 - cur);
            __syncthreads();
        }

        float* muS = &As[0][0][0];
        float* lvS = &Bs[0][0][0];

        #pragma unroll
        for (int t = 0; t < 4; t++) {
            #pragma unroll
            for (int q = 0; q < 4; q++) {
                const int r  = (q < 2) ? r0 : r1;
                const int rL = r - bm_;
                const int colL = wn32 + (t << 3) + (tg << 1) + (q & 1);
                if (colL < 32) {
                    const float m_ = acc[t][q] + __ldg(&bmu[colL]);
                    mu_out[r * 32 + colL] = m_;
                    muS[rL * 33 + colL] = m_;
                } else {
                    const int cl = colL - 32;
                    const float l_ = acc[t][q] + __ldg(&blv[cl]);
                    lv_out[r * 32 + cl] = l_;
                    lvS[rL * 33 + cl] = l_;
                }
            }
        }
        __syncthreads();

        for (int e = tid; e < 64 * 32; e += 256) {
            const int rL = e >> 5, cl = e & 31;
            const int r = bm_ + rL;
            const float zv = fmaf(__ldg(&epsv[r * 32 + cl]),
                                  expf(0.5f * lvS[rL * 33 + cl]), muS[rL * 33 + cl]);
            zsm[rL][cl] = zv;
            q0[r * 320 + cl] = zv;
            q1[r * 288 + cl] = zv;
            q2[r * 288 + cl] = zv;
        }
        __syncthreads();
    }

    // Phase B: gate0 GEMM, K=299, N=64
    {
        constexpr int Ktot = IN0;
        constexpr int NT   = (Ktot + BK - 1) / BK;

        auto ldgA = [&](int t) {
            const int kt = t * BK;
            #pragma unroll
            for (int half = 0; half < 2; half++) {
                const int mL = amL + half * 32;
                const int m  = bm_ + mL;
                #pragma unroll
                for (int j = 0; j < 4; j++) {
                    const int ig = kt + akq + j;
                    float val = 0.f;
                    if (ig < 32)            val = zsm[mL][ig];
                    else if (ig < Ktot)     val = __ldg(&cc[m * FRAME + (ig - 32)]);
                    avv[half][j] = val;
                }
            }
        };
        auto ldgB = [&](int t) {
            const int kt = t * BK;
            #pragma unroll
            for (int half = 0; half < 2; half++) {
                const int kg = kt + bkL + half * 16;
                const bool kok = kg < Ktot;
                float4 v = make_float4(0.f, 0.f, 0.f, 0.f);
                if (kok)
                    v = __ldg(reinterpret_cast<const float4*>(gw0 + kg * 64 + bnb));
                bvv[half][0] = v.x; bvv[half][1] = v.y;
                bvv[half][2] = v.z; bvv[half][3] = v.w;
            }
        };

        float acc[4][4] = {};
        ldgA(0); ldgB(0);
        sts(0);
        __syncthreads();

        for (int t = 0; t < NT; t++) {
            const int cur = t & 1;
            const bool more = (t + 1 < NT);
            if (more) { ldgA(t + 1); ldgB(t + 1); }

            #pragma unroll
            for (int ks = 0; ks < 4; ks++) {
                const int kk = ks << 3;
                uint32_t a0 = __float_as_uint(As[cur][wm16 + gid    ][kk + tg    ]);
                uint32_t a1 = __float_as_uint(As[cur][wm16 + gid + 8][kk + tg    ]);
                uint32_t a2 = __float_as_uint(As[cur][wm16 + gid    ][kk + tg + 4]);
                uint32_t a3 = __float_as_uint(As[cur][wm16 + gid + 8][kk + tg + 4]);
                #pragma unroll
                for (int t4 = 0; t4 < 4; t4++) {
                    const int col = wn32 + (t4 << 3) + gid;
                    uint32_t b0 = __float_as_uint(Bs[cur][kk + tg    ][col]);
                    uint32_t b1 = __float_as_uint(Bs[cur][kk + tg + 4][col]);
                    asm volatile(
                        "mma.sync.aligned.m16n8k8.row.col.f32.tf32.tf32.f32 "
                        "{%0,%1,%2,%3}, {%4,%5,%6,%7}, {%8,%9}, {%0,%1,%2,%3};\n"
                        : "+f"(acc[t4][0]), "+f"(acc[t4][1]),
                          "+f"(acc[t4][2]), "+f"(acc[t4][3])
                        : "r"(a0), "r"(a1), "r"(a2), "r"(a3), "r"(b0), "r"(b1));
                }
            }
            if (more) sts(1 - cur);
            __syncthreads();
        }

        #pragma unroll
        for (int t = 0; t < 4; t++) {
            #pragma unroll
            for (int q = 0; q < 4; q++) {
                const int rL = ((q < 2) ? r0 : r1) - bm_;
                const int colL = wn32 + (t << 3) + (tg << 1) + (q & 1);
                g1s[rL][colL] = elu1(acc[t][q] + __ldg(&gb0[colL]));
            }
        }
        __syncthreads();
    }

    // Phase C: gate1 (64x64), w1 overlay on Bs
    {
        float* w1f = &Bs[0][0][0];
        for (int i = tid; i < 64 * 64; i += 256)
            w1f[(i >> 6) * 72 + (i & 63)] = __ldg(&gw1[i]);
        __syncthreads();

        float* g2f = &As[0][0][0];
        const int row = tid >> 2;
        const int cs  = tid & 3;
        float a16[16];
        #pragma unroll
        for (int j = 0; j < 16; j++) a16[j] = __ldg(&gb1[cs + (j << 2)]);
        #pragma unroll
        for (int k = 0; k < 64; k++) {
            const float gv = g1s[row][k];
            #pragma unroll
            for (int j = 0; j < 16; j++)
                a16[j] = fmaf(gv, w1f[k * 72 + cs + (j << 2)], a16[j]);
        }
        #pragma unroll
        for (int j = 0; j < 16; j++)
            g2f[row * 65 + cs + (j << 2)] = elu1(a16[j]);
        __syncthreads();
    }

    // Phase D: gate2 + softmax -> coeff
    if (tid < 64) {
        const float* g2f = &As[0][0][0];
        float lg[EXPERTS];
        #pragma unroll
        for (int e = 0; e < EXPERTS; e++) lg[e] = __ldg(&gb2[e]);
        #pragma unroll
        for (int k = 0; k < 64; k++) {
            const float gv = g2f[tid * 65 + k];
            #pragma unroll
            for (int e = 0; e < EXPERTS; e++)
                lg[e] = fmaf(gv, __ldg(&gw2[k * EXPERTS + e]), lg[e]);
        }
        float mx = lg[0];
        #pragma unroll
        for (int e = 1; e < EXPERTS; e++) mx = fmaxf(mx, lg[e]);
        float s = 0.f;
        #pragma unroll
        for (int e = 0; e < EXPERTS; e++) { lg[e] = expf(lg[e] - mx); s += lg[e]; }
        const float inv = 1.f / s;
        #pragma unroll
        for (int e = 0; e < EXPERTS; e++)
            coeff[(bm_ + tid) * EXPERTS + e] = lg[e] * inv;
    }
}

// ---------------- pack kernels ----------------
// q0: c -> cols [32, 320)
__global__ void pack_c(const float* __restrict__ c, float* __restrict__ q0)
{
    int idx = blockIdx.x * blockDim.x + threadIdx.x;
    if (idx >= BATCH * 288) return;
    const int r = idx / 288;
    const int col = 32 + idx % 288;
    q0[r * 320 + col] = (col < IN0) ? c[r * FRAME + (col - 32)] : 0.f;
}
// xc = [x|c|0], xh/xh2 get x cols + zero pads (h cols filled by enc kernels)
__global__ void pack_in(const float* __restrict__ x, const float* __restrict__ c,
                        float* __restrict__ xc, float* __restrict__ xh,
                        float* __restrict__ xh2)
{
    int idx = blockIdx.x * blockDim.x + threadIdx.x;
    if (idx >= BATCH * 544) return;
    const int r = idx / 544, col = idx % 544;
    if (col < FRAME) {
        const float xv = x[r * FRAME + col];
        xc[idx] = xv; xh[idx] = xv; xh2[idx] = xv;
    } else {
        xc[idx] = (col < 2 * FRAME) ? c[r * FRAME + (col - FRAME)] : 0.f;
        if (col >= FRAME + HIDDEN) {    // cols [523,544): pads
            xh[idx] = 0.f; xh2[idx] = 0.f;
        }
    }
}

// ---------------- launch ----------------
extern "C" void kernel_launch(void* const* d_in, const int* in_sizes, int n_in,
                              void* d_out, int out_size)
{
    const float* x       = (const float*)d_in[0];
    const float* c       = (const float*)d_in[1];
    const float* eps     = (const float*)d_in[2];
    const float* enc_w1  = (const float*)d_in[3];
    const float* enc_b1  = (const float*)d_in[4];
    const float* enc_w2  = (const float*)d_in[5];
    const float* enc_b2  = (const float*)d_in[6];
    const float* enc_wmu = (const float*)d_in[7];
    const float* enc_bmu = (const float*)d_in[8];
    const float* enc_wlv = (const float*)d_in[9];
    const float* enc_blv = (const float*)d_in[10];
    const float* gw0     = (const float*)d_in[11];
    const float* gb0     = (const float*)d_in[12];
    const float* gw1     = (const float*)d_in[13];
    const float* gb1     = (const float*)d_in[14];
    const float* gw2     = (const float*)d_in[15];
    const float* gb2     = (const float*)d_in[16];
    const float* w0      = (const float*)d_in[17];
    const float* b0      = (const float*)d_in[18];
    const float* w1      = (const float*)d_in[19];
    const float* b1      = (const float*)d_in[20];
    const float* w2      = (const float*)d_in[21];
    const float* b2      = (const float*)d_in[22];
    float* out = (float*)d_out;

    float *coef, *xc, *xh, *xh2, *q0, *q1, *q2;
    cudaGetSymbolAddress((void**)&coef, g_coef);
    cudaGetSymbolAddress((void**)&xc,   g_xc);
    cudaGetSymbolAddress((void**)&xh,   g_xh);
    cudaGetSymbolAddress((void**)&xh2,  g_xh2);
    cudaGetSymbolAddress((void**)&q0,   g_q0);
    cudaGetSymbolAddress((void**)&q1,   g_q1);
    cudaGetSymbolAddress((void**)&q2,   g_q2);

    const dim3 blk(256);
    const dim3 gridH(HIDDEN / 64, BATCH / 64);              // (4, 64)
    const dim3 grid1(1, BATCH / 64);                        // (1, 64)
    const dim3 gridO((OUTD + 63) / 64, BATCH / 64);         // (5, 64)

    // pack inputs
    pack_in<<<(BATCH * 544 + 255) / 256, 256>>>(x, c, xc, xh, xh2);
    pack_c<<<(BATCH * 288 + 255) / 256, 256>>>(c, q0);
    // encoder layer 1: h1 = elu([x,c] @ w1 + b1) -> xh cols [267,523)
    gemm_p<HIDDEN, 2*FRAME, 544, 544, 1, 1><<<gridH, blk>>>(
        xc, nullptr, enc_w1, enc_b1, xh + FRAME, 544);
    // encoder layer 2: h2 = elu([x,h1] @ w2 + b2) -> xh2 cols [267,523)
    gemm_p<HIDDEN, FRAME+HIDDEN, 544, 544, 1, 1><<<gridH, blk>>>(
        xh, nullptr, enc_w2, enc_b2, xh2 + FRAME, 544);
    // mid2: mu/lv + z + gate0 + gate1 + gate2 + softmax (one launch)
    mid2<<<grid1, blk>>>(
        xh2, enc_wmu, enc_bmu, enc_wlv, enc_blv, eps, c,
        gw0, gb0, gw1, gb1, gw2, gb2,
        out + OFF_MU, out + OFF_LV, q0, q1, q2, coef);
    // MoE decoder layer 0: DIN 299 (pad 320) -> d1 into q1 cols [32,288)
    gemm_p<HIDDEN, IN0, 320, 320, EXPERTS, 1><<<gridH, blk>>>(
        q0, coef, w0, b0, q1 + 32, IN1);
    // MoE decoder layer 1: DIN 288 exact -> d2 into q2 cols [32,288)
    gemm_p<HIDDEN, IN1, 288, 288, EXPERTS, 1><<<gridH, blk>>>(
        q1, coef, w1, b1, q2 + 32, IN1);
    // MoE decoder layer 2 (no act): N=267 -> output
    gemm_p<OUTD, IN1, 288, 288, EXPERTS, 0><<<gridO, blk>>>(
        q2, coef, w2, b2, out, OUTD);
}

// round 17
// speedup vs baseline: 1.5100x; 1.0383x over previous
#include <cuda_runtime.h>
#include <cstdint>

// ---------------- problem constants ----------------
#define BATCH   4096
#define FRAME   267
#define LATENT  32
#define HIDDEN  256
#define GATE_H  64
#define EXPERTS 6
#define IN0     (LATENT + FRAME)    // 299
#define IN1     (LATENT + HIDDEN)   // 288
#define OUTD    FRAME               // 267

#define OFF_MU  (BATCH * OUTD)
#define OFF_LV  (OFF_MU + BATCH * LATENT)

// ---------------- scratch (allocation-free) ----------------
__device__ float g_coef[BATCH * EXPERTS];
// packed, 16B-aligned input rows
__device__ __align__(16) float g_xc [BATCH * 544];  // [x | c | 0pad]
__device__ __align__(16) float g_xh [BATCH * 544];  // [x | h1 | 0pad]
__device__ __align__(16) float g_xh2[BATCH * 544];  // [x | h2 | 0pad]
// packed decoder inputs
__device__ __align__(16) float g_q0[BATCH * 320];   // [z | c | 0pad]
__device__ __align__(16) float g_q1[BATCH * 288];   // [z | d1]
__device__ __align__(16) float g_q2[BATCH * 288];   // [z | d2]
// split-K partial buffers (expert halves)
__device__ __align__(16) float g_p0[BATCH * 288];
__device__ __align__(16) float g_p1[BATCH * 288];

__device__ __forceinline__ float elu1(float x) { return x > 0.f ? x : expm1f(x); }

__device__ __forceinline__ float tf32r(float x) {
    float y;
    asm("cvt.rna.tf32.f32 %0, %1;" : "=f"(y) : "f"(x));
    return y;
}

#define BK 32

// ============================================================
// Unified packed GEMM (R16-proven), E_=1 path for encoders.
// Tile 64x64x32, 256 threads, 8 warps (4m x 2n), double-buffered.
// ============================================================
template<int N_, int DINR_, int DINP_, int LDA_, int E_, int ACT_>
__global__ __launch_bounds__(256) void gemm_p(
    const float* __restrict__ A,
    const float* __restrict__ coeff,
    const float* __restrict__ W, const float* __restrict__ bias,
    float* __restrict__ C, int ldc)
{
    constexpr int TPE = DINP_ / 32;
    constexpr int NT  = E_ * TPE;
    __shared__ __align__(16) float As[2][64][36];
    __shared__ __align__(16) float Bs[2][32][72];

    const int tid  = threadIdx.x;
    const int lane = tid & 31;
    const int wid  = tid >> 5;
    const int wm16 = (wid >> 1) << 4;
    const int wn32 = (wid & 1) << 5;
    const int gid  = lane >> 2;
    const int tg   = lane & 3;

    const int bm_ = blockIdx.y * 64;
    const int bn_ = blockIdx.x * 64;

    const int amL = tid >> 3;
    const int akq = (tid & 7) << 2;
    const int bkL = tid >> 4;
    const int bnb = (tid & 15) << 2;

    const float* Ar0  = A + (size_t)(bm_ + amL) * LDA_;
    const float* Ar1  = Ar0 + (size_t)32 * LDA_;
    const float* cf0p = (E_ > 1) ? coeff + (bm_ + amL) * E_ : nullptr;
    const float* cf1p = (E_ > 1) ? cf0p + 32 * E_ : nullptr;

    float avv[2][4], bvv[2][4];

    auto ldgA = [&](int t) {
        const int e  = (E_ > 1) ? (t / TPE) : 0;
        const int i0 = (t - e * TPE) * 32 + akq;
        const float4 v0 = __ldg(reinterpret_cast<const float4*>(Ar0 + i0));
        const float4 v1 = __ldg(reinterpret_cast<const float4*>(Ar1 + i0));
        if (E_ > 1) {
            const float c0 = __ldg(&cf0p[e]);
            const float c1 = __ldg(&cf1p[e]);
            avv[0][0] = v0.x * c0; avv[0][1] = v0.y * c0;
            avv[0][2] = v0.z * c0; avv[0][3] = v0.w * c0;
            avv[1][0] = v1.x * c1; avv[1][1] = v1.y * c1;
            avv[1][2] = v1.z * c1; avv[1][3] = v1.w * c1;
        } else {
            avv[0][0] = v0.x; avv[0][1] = v0.y; avv[0][2] = v0.z; avv[0][3] = v0.w;
            avv[1][0] = v1.x; avv[1][1] = v1.y; avv[1][2] = v1.z; avv[1][3] = v1.w;
        }
    };
    auto ldgB = [&](int t) {
        const int e  = (E_ > 1) ? (t / TPE) : 0;
        const int k0 = (t - e * TPE) * 32;
        const float* We = W + (size_t)e * DINR_ * N_;
        #pragma unroll
        for (int half = 0; half < 2; half++) {
            const int kl = k0 + bkL + half * 16;
            const bool kok = (DINR_ == DINP_) || (kl < DINR_);
            if ((N_ % 64) == 0) {
                float4 v = make_float4(0.f, 0.f, 0.f, 0.f);
                if (kok)
                    v = __ldg(reinterpret_cast<const float4*>(We + (size_t)kl * N_ + bn_ + bnb));
                bvv[half][0] = v.x; bvv[half][1] = v.y; bvv[half][2] = v.z; bvv[half][3] = v.w;
            } else {
                #pragma unroll
                for (int j = 0; j < 4; j++) {
                    const int n = bn_ + bnb + j;
                    float v = 0.f;
                    if (kok && n < N_) v = __ldg(&We[(size_t)kl * N_ + n]);
                    bvv[half][j] = v;
                }
            }
        }
    };
    auto sts = [&](int buf) {
        #pragma unroll
        for (int half = 0; half < 2; half++) {
            const float4 t4 = make_float4(tf32r(avv[half][0]), tf32r(avv[half][1]),
                                          tf32r(avv[half][2]), tf32r(avv[half][3]));
            *reinterpret_cast<float4*>(&As[buf][amL + half * 32][akq]) = t4;
        }
        #pragma unroll
        for (int half = 0; half < 2; half++) {
            const float4 t4 = make_float4(tf32r(bvv[half][0]), tf32r(bvv[half][1]),
                                          tf32r(bvv[half][2]), tf32r(bvv[half][3]));
            *reinterpret_cast<float4*>(&Bs[buf][bkL + half * 16][bnb]) = t4;
        }
    };

    float acc[4][4] = {};

    ldgA(0); ldgB(0);
    sts(0);
    __syncthreads();

    for (int t = 0; t < NT; t++) {
        const int cur = t & 1;
        const bool more = (t + 1 < NT);
        if (more) { ldgA(t + 1); ldgB(t + 1); }

        #pragma unroll
        for (int ks = 0; ks < 4; ks++) {
            const int kk = ks << 3;
            uint32_t a0 = __float_as_uint(As[cur][wm16 + gid    ][kk + tg    ]);
            uint32_t a1 = __float_as_uint(As[cur][wm16 + gid + 8][kk + tg    ]);
            uint32_t a2 = __float_as_uint(As[cur][wm16 + gid    ][kk + tg + 4]);
            uint32_t a3 = __float_as_uint(As[cur][wm16 + gid + 8][kk + tg + 4]);
            #pragma unroll
            for (int t4i = 0; t4i < 4; t4i++) {
                const int col = wn32 + (t4i << 3) + gid;
                uint32_t b0 = __float_as_uint(Bs[cur][kk + tg    ][col]);
                uint32_t b1 = __float_as_uint(Bs[cur][kk + tg + 4][col]);
                asm volatile(
                    "mma.sync.aligned.m16n8k8.row.col.f32.tf32.tf32.f32 "
                    "{%0,%1,%2,%3}, {%4,%5,%6,%7}, {%8,%9}, {%0,%1,%2,%3};\n"
                    : "+f"(acc[t4i][0]), "+f"(acc[t4i][1]),
                      "+f"(acc[t4i][2]), "+f"(acc[t4i][3])
                    : "r"(a0), "r"(a1), "r"(a2), "r"(a3), "r"(b0), "r"(b1));
            }
        }
        if (more) sts(1 - cur);
        __syncthreads();
    }

    const int r0 = bm_ + wm16 + gid;
    const int r1 = r0 + 8;
    float cf0[E_], cf1[E_];
    if (E_ > 1) {
        #pragma unroll
        for (int e = 0; e < E_; e++) {
            cf0[e] = coeff[r0 * E_ + e];
            cf1[e] = coeff[r1 * E_ + e];
        }
    }

    #pragma unroll
    for (int t = 0; t < 4; t++) {
        #pragma unroll
        for (int q = 0; q < 4; q++) {
            const int r  = (q < 2) ? r0 : r1;
            const int colL = wn32 + (t << 3) + (tg << 1) + (q & 1);
            const int cG = bn_ + colL;
            if ((N_ % 64) == 0 || cG < N_) {
                float bb;
                if (E_ > 1) {
                    const float* cf = (q < 2) ? cf0 : cf1;
                    bb = 0.f;
                    #pragma unroll
                    for (int e = 0; e < E_; e++)
                        bb = fmaf(cf[e], __ldg(&bias[e * N_ + cG]), bb);
                } else {
                    bb = __ldg(&bias[cG]);
                }
                float v = acc[t][q] + bb;
                if (ACT_ == 1) v = elu1(v);
                C[(size_t)r * ldc + cG] = v;
            }
        }
    }
}

// ============================================================
// Split-K decoder GEMM: blockIdx.z selects expert half (0: e0-2,
// 1: e3-5). Same proven tile/loader; epilogue writes coeff-weighted
// PARTIAL sums (no bias, no act) to pb[z]. Grid (N/64, 64, 2).
// ============================================================
template<int N_, int DINR_, int DINP_, int LDA_>
__global__ __launch_bounds__(256) void dec_half(
    const float* __restrict__ A,
    const float* __restrict__ coeff,
    const float* __restrict__ W,
    float* __restrict__ pb0, float* __restrict__ pb1)
{
    constexpr int EH  = EXPERTS / 2;     // 3
    constexpr int TPE = DINP_ / 32;
    constexpr int NT  = EH * TPE;
    __shared__ __align__(16) float As[2][64][36];
    __shared__ __align__(16) float Bs[2][32][72];

    const int tid  = threadIdx.x;
    const int lane = tid & 31;
    const int wid  = tid >> 5;
    const int wm16 = (wid >> 1) << 4;
    const int wn32 = (wid & 1) << 5;
    const int gid  = lane >> 2;
    const int tg   = lane & 3;

    const int bm_ = blockIdx.y * 64;
    const int bn_ = blockIdx.x * 64;
    const int eo  = blockIdx.z * EH;     // expert offset 0 or 3

    const int amL = tid >> 3;
    const int akq = (tid & 7) << 2;
    const int bkL = tid >> 4;
    const int bnb = (tid & 15) << 2;

    const float* Ar0  = A + (size_t)(bm_ + amL) * LDA_;
    const float* Ar1  = Ar0 + (size_t)32 * LDA_;
    const float* cf0p = coeff + (bm_ + amL) * EXPERTS + eo;
    const float* cf1p = cf0p + 32 * EXPERTS;
    const float* Wo   = W + (size_t)eo * DINR_ * N_;

    float avv[2][4], bvv[2][4];

    auto ldgA = [&](int t) {
        const int e  = t / TPE;
        const int i0 = (t - e * TPE) * 32 + akq;
        const float c0 = __ldg(&cf0p[e]);
        const float c1 = __ldg(&cf1p[e]);
        const float4 v0 = __ldg(reinterpret_cast<const float4*>(Ar0 + i0));
        const float4 v1 = __ldg(reinterpret_cast<const float4*>(Ar1 + i0));
        avv[0][0] = v0.x * c0; avv[0][1] = v0.y * c0;
        avv[0][2] = v0.z * c0; avv[0][3] = v0.w * c0;
        avv[1][0] = v1.x * c1; avv[1][1] = v1.y * c1;
        avv[1][2] = v1.z * c1; avv[1][3] = v1.w * c1;
    };
    auto ldgB = [&](int t) {
        const int e  = t / TPE;
        const int k0 = (t - e * TPE) * 32;
        const float* We = Wo + (size_t)e * DINR_ * N_;
        #pragma unroll
        for (int half = 0; half < 2; half++) {
            const int kl = k0 + bkL + half * 16;
            const bool kok = (DINR_ == DINP_) || (kl < DINR_);
            if ((N_ % 64) == 0) {
                float4 v = make_float4(0.f, 0.f, 0.f, 0.f);
                if (kok)
                    v = __ldg(reinterpret_cast<const float4*>(We + (size_t)kl * N_ + bn_ + bnb));
                bvv[half][0] = v.x; bvv[half][1] = v.y; bvv[half][2] = v.z; bvv[half][3] = v.w;
            } else {
                #pragma unroll
                for (int j = 0; j < 4; j++) {
                    const int n = bn_ + bnb + j;
                    float v = 0.f;
                    if (kok && n < N_) v = __ldg(&We[(size_t)kl * N_ + n]);
                    bvv[half][j] = v;
                }
            }
        }
    };
    auto sts = [&](int buf) {
        #pragma unroll
        for (int half = 0; half < 2; half++) {
            const float4 t4 = make_float4(tf32r(avv[half][0]), tf32r(avv[half][1]),
                                          tf32r(avv[half][2]), tf32r(avv[half][3]));
            *reinterpret_cast<float4*>(&As[buf][amL + half * 32][akq]) = t4;
        }
        #pragma unroll
        for (int half = 0; half < 2; half++) {
            const float4 t4 = make_float4(tf32r(bvv[half][0]), tf32r(bvv[half][1]),
                                          tf32r(bvv[half][2]), tf32r(bvv[half][3]));
            *reinterpret_cast<float4*>(&Bs[buf][bkL + half * 16][bnb]) = t4;
        }
    };

    float acc[4][4] = {};

    ldgA(0); ldgB(0);
    sts(0);
    __syncthreads();

    for (int t = 0; t < NT; t++) {
        const int cur = t & 1;
        const bool more = (t + 1 < NT);
        if (more) { ldgA(t + 1); ldgB(t + 1); }

        #pragma unroll
        for (int ks = 0; ks < 4; ks++) {
            const int kk = ks << 3;
            uint32_t a0 = __float_as_uint(As[cur][wm16 + gid    ][kk + tg    ]);
            uint32_t a1 = __float_as_uint(As[cur][wm16 + gid + 8][kk + tg    ]);
            uint32_t a2 = __float_as_uint(As[cur][wm16 + gid    ][kk + tg + 4]);
            uint32_t a3 = __float_as_uint(As[cur][wm16 + gid + 8][kk + tg + 4]);
            #pragma unroll
            for (int t4i = 0; t4i < 4; t4i++) {
                const int col = wn32 + (t4i << 3) + gid;
                uint32_t b0 = __float_as_uint(Bs[cur][kk + tg    ][col]);
                uint32_t b1 = __float_as_uint(Bs[cur][kk + tg + 4][col]);
                asm volatile(
                    "mma.sync.aligned.m16n8k8.row.col.f32.tf32.tf32.f32 "
                    "{%0,%1,%2,%3}, {%4,%5,%6,%7}, {%8,%9}, {%0,%1,%2,%3};\n"
                    : "+f"(acc[t4i][0]), "+f"(acc[t4i][1]),
                      "+f"(acc[t4i][2]), "+f"(acc[t4i][3])
                    : "r"(a0), "r"(a1), "r"(a2), "r"(a3), "r"(b0), "r"(b1));
            }
        }
        if (more) sts(1 - cur);
        __syncthreads();
    }

    float* pb = (blockIdx.z == 0) ? pb0 : pb1;
    const int r0 = bm_ + wm16 + gid;
    const int r1 = r0 + 8;
    #pragma unroll
    for (int t = 0; t < 4; t++) {
        #pragma unroll
        for (int q = 0; q < 4; q++) {
            const int r  = (q < 2) ? r0 : r1;
            const int colL = wn32 + (t << 3) + (tg << 1) + (q & 1);
            const int cG = bn_ + colL;
            if ((N_ % 64) == 0 || cG < N_)
                pb[(size_t)r * N_ + cG] = acc[t][q];
        }
    }
}

// combine: C = act(p0 + p1 + coeff@bias)
template<int N_, int ACT_>
__global__ void combine(const float* __restrict__ p0, const float* __restrict__ p1,
                        const float* __restrict__ coeff, const float* __restrict__ bias,
                        float* __restrict__ C, int ldc)
{
    const int r = blockIdx.y;
    const int n = blockIdx.x * 256 + threadIdx.x;
    if (n >= N_) return;
    float cf[EXPERTS];
    #pragma unroll
    for (int e = 0; e < EXPERTS; e++) cf[e] = __ldg(&coeff[r * EXPERTS + e]);
    float bb = 0.f;
    #pragma unroll
    for (int e = 0; e < EXPERTS; e++)
        bb = fmaf(cf[e], __ldg(&bias[e * N_ + n]), bb);
    float v = __ldg(&p0[(size_t)r * N_ + n]) + __ldg(&p1[(size_t)r * N_ + n]) + bb;
    if (ACT_ == 1) v = elu1(v);
    C[(size_t)r * ldc + n] = v;
}

// ============================================================
// mid2 — R16-passing VERBATIM.
// ============================================================
__global__ __launch_bounds__(256) void mid2(
    const float* __restrict__ xh2,
    const float* __restrict__ wmu, const float* __restrict__ bmu,
    const float* __restrict__ wlv, const float* __restrict__ blv,
    const float* __restrict__ epsv, const float* __restrict__ cc,
    const float* __restrict__ gw0, const float* __restrict__ gb0,
    const float* __restrict__ gw1, const float* __restrict__ gb1,
    const float* __restrict__ gw2, const float* __restrict__ gb2,
    float* __restrict__ mu_out, float* __restrict__ lv_out,
    float* __restrict__ q0, float* __restrict__ q1, float* __restrict__ q2,
    float* __restrict__ coeff)
{
    __shared__ float As[2][64][36];
    __shared__ float Bs[2][32][72];
    __shared__ float g1s[64][65];
    __shared__ float zsm[64][33];

    const int tid  = threadIdx.x;
    const int lane = tid & 31;
    const int wid  = tid >> 5;
    const int wm16 = (wid >> 1) << 4;
    const int wn32 = (wid & 1) << 5;
    const int gid  = lane >> 2;
    const int tg   = lane & 3;

    const int bm_ = blockIdx.y * 64;

    const int amL = tid >> 3;
    const int akq = (tid & 7) << 2;
    const int bkL = tid >> 4;
    const int bnb = (tid & 15) << 2;

    const int r0 = bm_ + wm16 + gid;
    const int r1 = r0 + 8;

    float avv[2][4], bvv[2][4];

    auto sts = [&](int buf) {
        #pragma unroll
        for (int half = 0; half < 2; half++) {
            const int mL = amL + half * 32;
            #pragma unroll
            for (int j = 0; j < 4; j++)
                As[buf][mL][akq + j] = tf32r(avv[half][j]);
        }
        #pragma unroll
        for (int half = 0; half < 2; half++) {
            const int kL = bkL + half * 16;
            #pragma unroll
            for (int j = 0; j < 4; j++)
                Bs[buf][kL][bnb + j] = tf32r(bvv[half][j]);
        }
    };

    // Phase A: dual GEMM mu|lv, K=523 (padded 544)
    {
        constexpr int Ktot = FRAME + HIDDEN;
        constexpr int NT   = 544 / BK;

        const float* Ar0 = xh2 + (size_t)(bm_ + amL) * 544;
        const float* Ar1 = Ar0 + (size_t)32 * 544;

        auto ldgA = [&](int t) {
            const int i0 = t * BK + akq;
            const float4 v0 = __ldg(reinterpret_cast<const float4*>(Ar0 + i0));
            const float4 v1 = __ldg(reinterpret_cast<const float4*>(Ar1 + i0));
            avv[0][0] = v0.x; avv[0][1] = v0.y; avv[0][2] = v0.z; avv[0][3] = v0.w;
            avv[1][0] = v1.x; avv[1][1] = v1.y; avv[1][2] = v1.z; avv[1][3] = v1.w;
        };
        auto ldgB = [&](int t) {
            const int kt = t * BK;
            #pragma unroll
            for (int half = 0; half < 2; half++) {
                const int kg = kt + bkL + half * 16;
                const bool kok = kg < Ktot;
                const float* base = (bnb < 32) ? (wmu + kg * 32 + bnb)
                                               : (wlv + kg * 32 + (bnb - 32));
                float4 v = make_float4(0.f, 0.f, 0.f, 0.f);
                if (kok) v = __ldg(reinterpret_cast<const float4*>(base));
                bvv[half][0] = v.x; bvv[half][1] = v.y;
                bvv[half][2] = v.z; bvv[half][3] = v.w;
            }
        };

        float acc[4][4] = {};
        ldgA(0); ldgB(0);
        sts(0);
        __syncthreads();

        for (int t = 0; t < NT; t++) {
            const int cur = t & 1;
            const bool more = (t + 1 < NT);
            if (more) { ldgA(t + 1); ldgB(t + 1); }

            #pragma unroll
            for (int ks = 0; ks < 4; ks++) {
                const int kk = ks << 3;
                uint32_t a0 = __float_as_uint(As[cur][wm16 + gid    ][kk + tg    ]);
                uint32_t a1 = __float_as_uint(As[cur][wm16 + gid + 8][kk + tg    ]);
                uint32_t a2 = __float_as_uint(As[cur][wm16 + gid    ][kk + tg + 4]);
                uint32_t a3 = __float_as_uint(As[cur][wm16 + gid + 8][kk + tg + 4]);
                #pragma unroll
                for (int t4 = 0; t4 < 4; t4++) {
                    const int col = wn32 + (t4 << 3) + gid;
                    uint32_t b0 = __float_as_uint(Bs[cur][kk + tg    ][col]);
                    uint32_t b1 = __float_as_uint(Bs[cur][kk + tg + 4][col]);
                    asm volatile(
                        "mma.sync.aligned.m16n8k8.row.col.f32.tf32.tf32.f32 "
                        "{%0,%1,%2,%3}, {%4,%5,%6,%7}, {%8,%9}, {%0,%1,%2,%3};\n"
                        : "+f"(acc[t4][0]), "+f"(acc[t4][1]),
                          "+f"(acc[t4][2]), "+f"(acc[t4][3])
                        : "r"(a0), "r"(a1), "r"(a2), "r"(a3), "r"(b0), "r"(b1));
                }
            }
            if (more) sts(1 - cur);
            __syncthreads();
        }

        float* muS = &As[0][0][0];
        float* lvS = &Bs[0][0][0];

        #pragma unroll
        for (int t = 0; t < 4; t++) {
            #pragma unroll
            for (int q = 0; q < 4; q++) {
                const int r  = (q < 2) ? r0 : r1;
                const int rL = r - bm_;
                const int colL = wn32 + (t << 3) + (tg << 1) + (q & 1);
                if (colL < 32) {
                    const float m_ = acc[t][q] + __ldg(&bmu[colL]);
                    mu_out[r * 32 + colL] = m_;
                    muS[rL * 33 + colL] = m_;
                } else {
                    const int cl = colL - 32;
                    const float l_ = acc[t][q] + __ldg(&blv[cl]);
                    lv_out[r * 32 + cl] = l_;
                    lvS[rL * 33 + cl] = l_;
                }
            }
        }
        __syncthreads();

        for (int e = tid; e < 64 * 32; e += 256) {
            const int rL = e >> 5, cl = e & 31;
            const int r = bm_ + rL;
            const float zv = fmaf(__ldg(&epsv[r * 32 + cl]),
                                  expf(0.5f * lvS[rL * 33 + cl]), muS[rL * 33 + cl]);
            zsm[rL][cl] = zv;
            q0[r * 320 + cl] = zv;
            q1[r * 288 + cl] = zv;
            q2[r * 288 + cl] = zv;
        }
        __syncthreads();
    }

    // Phase B: gate0 GEMM, K=299, N=64
    {
        constexpr int Ktot = IN0;
        constexpr int NT   = (Ktot + BK - 1) / BK;

        auto ldgA = [&](int t) {
            const int kt = t * BK;
            #pragma unroll
            for (int half = 0; half < 2; half++) {
                const int mL = amL + half * 32;
                const int m  = bm_ + mL;
                #pragma unroll
                for (int j = 0; j < 4; j++) {
                    const int ig = kt + akq + j;
                    float val = 0.f;
                    if (ig < 32)            val = zsm[mL][ig];
                    else if (ig < Ktot)     val = __ldg(&cc[m * FRAME + (ig - 32)]);
                    avv[half][j] = val;
                }
            }
        };
        auto ldgB = [&](int t) {
            const int kt = t * BK;
            #pragma unroll
            for (int half = 0; half < 2; half++) {
                const int kg = kt + bkL + half * 16;
                const bool kok = kg < Ktot;
                float4 v = make_float4(0.f, 0.f, 0.f, 0.f);
                if (kok)
                    v = __ldg(reinterpret_cast<const float4*>(gw0 + kg * 64 + bnb));
                bvv[half][0] = v.x; bvv[half][1] = v.y;
                bvv[half][2] = v.z; bvv[half][3] = v.w;
            }
        };

        float acc[4][4] = {};
        ldgA(0); ldgB(0);
        sts(0);
        __syncthreads();

        for (int t = 0; t < NT; t++) {
            const int cur = t & 1;
            const bool more = (t + 1 < NT);
            if (more) { ldgA(t + 1); ldgB(t + 1); }

            #pragma unroll
            for (int ks = 0; ks < 4; ks++) {
                const int kk = ks << 3;
                uint32_t a0 = __float_as_uint(As[cur][wm16 + gid    ][kk + tg    ]);
                uint32_t a1 = __float_as_uint(As[cur][wm16 + gid + 8][kk + tg    ]);
                uint32_t a2 = __float_as_uint(As[cur][wm16 + gid    ][kk + tg + 4]);
                uint32_t a3 = __float_as_uint(As[cur][wm16 + gid + 8][kk + tg + 4]);
                #pragma unroll
                for (int t4 = 0; t4 < 4; t4++) {
                    const int col = wn32 + (t4 << 3) + gid;
                    uint32_t b0 = __float_as_uint(Bs[cur][kk + tg    ][col]);
                    uint32_t b1 = __float_as_uint(Bs[cur][kk + tg + 4][col]);
                    asm volatile(
                        "mma.sync.aligned.m16n8k8.row.col.f32.tf32.tf32.f32 "
                        "{%0,%1,%2,%3}, {%4,%5,%6,%7}, {%8,%9}, {%0,%1,%2,%3};\n"
                        : "+f"(acc[t4][0]), "+f"(acc[t4][1]),
                          "+f"(acc[t4][2]), "+f"(acc[t4][3])
                        : "r"(a0), "r"(a1), "r"(a2), "r"(a3), "r"(b0), "r"(b1));
                }
            }
            if (more) sts(1 - cur);
            __syncthreads();
        }

        #pragma unroll
        for (int t = 0; t < 4; t++) {
            #pragma unroll
            for (int q = 0; q < 4; q++) {
                const int rL = ((q < 2) ? r0 : r1) - bm_;
                const int colL = wn32 + (t << 3) + (tg << 1) + (q & 1);
                g1s[rL][colL] = elu1(acc[t][q] + __ldg(&gb0[colL]));
            }
        }
        __syncthreads();
    }

    // Phase C: gate1 (64x64), w1 overlay on Bs
    {
        float* w1f = &Bs[0][0][0];
        for (int i = tid; i < 64 * 64; i += 256)
            w1f[(i >> 6) * 72 + (i & 63)] = __ldg(&gw1[i]);
        __syncthreads();

        float* g2f = &As[0][0][0];
        const int row = tid >> 2;
        const int cs  = tid & 3;
        float a16[16];
        #pragma unroll
        for (int j = 0; j < 16; j++) a16[j] = __ldg(&gb1[cs + (j << 2)]);
        #pragma unroll
        for (int k = 0; k < 64; k++) {
            const float gv = g1s[row][k];
            #pragma unroll
            for (int j = 0; j < 16; j++)
                a16[j] = fmaf(gv, w1f[k * 72 + cs + (j << 2)], a16[j]);
        }
        #pragma unroll
        for (int j = 0; j < 16; j++)
            g2f[row * 65 + cs + (j << 2)] = elu1(a16[j]);
        __syncthreads();
    }

    // Phase D: gate2 + softmax -> coeff
    if (tid < 64) {
        const float* g2f = &As[0][0][0];
        float lg[EXPERTS];
        #pragma unroll
        for (int e = 0; e < EXPERTS; e++) lg[e] = __ldg(&gb2[e]);
        #pragma unroll
        for (int k = 0; k < 64; k++) {
            const float gv = g2f[tid * 65 + k];
            #pragma unroll
            for (int e = 0; e < EXPERTS; e++)
                lg[e] = fmaf(gv, __ldg(&gw2[k * EXPERTS + e]), lg[e]);
        }
        float mx = lg[0];
        #pragma unroll
        for (int e = 1; e < EXPERTS; e++) mx = fmaxf(mx, lg[e]);
        float s = 0.f;
        #pragma unroll
        for (int e = 0; e < EXPERTS; e++) { lg[e] = expf(lg[e] - mx); s += lg[e]; }
        const float inv = 1.f / s;
        #pragma unroll
        for (int e = 0; e < EXPERTS; e++)
            coeff[(bm_ + tid) * EXPERTS + e] = lg[e] * inv;
    }
}

// ---------------- pack kernels (R16 verbatim) ----------------
__global__ void pack_c(const float* __restrict__ c, float* __restrict__ q0)
{
    int idx = blockIdx.x * blockDim.x + threadIdx.x;
    if (idx >= BATCH * 288) return;
    const int r = idx / 288;
    const int col = 32 + idx % 288;
    q0[r * 320 + col] = (col < IN0) ? c[r * FRAME + (col - 32)] : 0.f;
}
__global__ void pack_in(const float* __restrict__ x, const float* __restrict__ c,
                        float* __restrict__ xc, float* __restrict__ xh,
                        float* __restrict__ xh2)
{
    int idx = blockIdx.x * blockDim.x + threadIdx.x;
    if (idx >= BATCH * 544) return;
    const int r = idx / 544, col = idx % 544;
    if (col < FRAME) {
        const float xv = x[r * FRAME + col];
        xc[idx] = xv; xh[idx] = xv; xh2[idx] = xv;
    } else {
        xc[idx] = (col < 2 * FRAME) ? c[r * FRAME + (col - FRAME)] : 0.f;
        if (col >= FRAME + HIDDEN) {
            xh[idx] = 0.f; xh2[idx] = 0.f;
        }
    }
}

// ---------------- launch ----------------
extern "C" void kernel_launch(void* const* d_in, const int* in_sizes, int n_in,
                              void* d_out, int out_size)
{
    const float* x       = (const float*)d_in[0];
    const float* c       = (const float*)d_in[1];
    const float* eps     = (const float*)d_in[2];
    const float* enc_w1  = (const float*)d_in[3];
    const float* enc_b1  = (const float*)d_in[4];
    const float* enc_w2  = (const float*)d_in[5];
    const float* enc_b2  = (const float*)d_in[6];
    const float* enc_wmu = (const float*)d_in[7];
    const float* enc_bmu = (const float*)d_in[8];
    const float* enc_wlv = (const float*)d_in[9];
    const float* enc_blv = (const float*)d_in[10];
    const float* gw0     = (const float*)d_in[11];
    const float* gb0     = (const float*)d_in[12];
    const float* gw1     = (const float*)d_in[13];
    const float* gb1     = (const float*)d_in[14];
    const float* gw2     = (const float*)d_in[15];
    const float* gb2     = (const float*)d_in[16];
    const float* w0      = (const float*)d_in[17];
    const float* b0      = (const float*)d_in[18];
    const float* w1      = (const float*)d_in[19];
    const float* b1      = (const float*)d_in[20];
    const float* w2      = (const float*)d_in[21];
    const float* b2      = (const float*)d_in[22];
    float* out = (float*)d_out;

    float *coef, *xc, *xh, *xh2, *q0, *q1, *q2, *p0, *p1;
    cudaGetSymbolAddress((void**)&coef, g_coef);
    cudaGetSymbolAddress((void**)&xc,   g_xc);
    cudaGetSymbolAddress((void**)&xh,   g_xh);
    cudaGetSymbolAddress((void**)&xh2,  g_xh2);
    cudaGetSymbolAddress((void**)&q0,   g_q0);
    cudaGetSymbolAddress((void**)&q1,   g_q1);
    cudaGetSymbolAddress((void**)&q2,   g_q2);
    cudaGetSymbolAddress((void**)&p0,   g_p0);
    cudaGetSymbolAddress((void**)&p1,   g_p1);

    const dim3 blk(256);
    const dim3 gridH(HIDDEN / 64, BATCH / 64);               // (4, 64)
    const dim3 grid1(1, BATCH / 64);                         // (1, 64)
    const dim3 gridHs(HIDDEN / 64, BATCH / 64, 2);           // (4, 64, 2) = 512
    const dim3 gridOs((OUTD + 63) / 64, BATCH / 64, 2);      // (5, 64, 2) = 640
    const dim3 gridC1(1, BATCH);                             // combine N=256
    const dim3 gridC2(2, BATCH);                             // combine N=267

    // pack inputs
    pack_in<<<(BATCH * 544 + 255) / 256, 256>>>(x, c, xc, xh, xh2);
    pack_c<<<(BATCH * 288 + 255) / 256, 256>>>(c, q0);
    // encoder layer 1: h1 -> xh cols [267,523)
    gemm_p<HIDDEN, 2*FRAME, 544, 544, 1, 1><<<gridH, blk>>>(
        xc, nullptr, enc_w1, enc_b1, xh + FRAME, 544);
    // encoder layer 2: h2 -> xh2 cols [267,523)
    gemm_p<HIDDEN, FRAME+HIDDEN, 544, 544, 1, 1><<<gridH, blk>>>(
        xh, nullptr, enc_w2, enc_b2, xh2 + FRAME, 544);
    // mid2: mu/lv + z + gate0 + gate1 + gate2 + softmax
    mid2<<<grid1, blk>>>(
        xh2, enc_wmu, enc_bmu, enc_wlv, enc_blv, eps, c,
        gw0, gb0, gw1, gb1, gw2, gb2,
        out + OFF_MU, out + OFF_LV, q0, q1, q2, coef);
    // MoE decoder layer 0 (split-K by expert halves) -> d1 in q1
    dec_half<HIDDEN, IN0, 320, 320><<<gridHs, blk>>>(q0, coef, w0, p0, p1);
    combine<HIDDEN, 1><<<gridC1, blk>>>(p0, p1, coef, b0, q1 + 32, IN1);
    // MoE decoder layer 1 -> d2 in q2
    dec_half<HIDDEN, IN1, 288, 288><<<gridHs, blk>>>(q1, coef, w1, p0, p1);
    combine<HIDDEN, 1><<<gridC1, blk>>>(p0, p1, coef, b1, q2 + 32, IN1);
    // MoE decoder layer 2 -> output (no act)
    dec_half<OUTD, IN1, 288, 288><<<gridOs, blk>>>(q2, coef, w2, p0, p1);
    combine<OUTD, 0><<<gridC2, blk>>>(p0, p1, coef, b2, out, OUTD);
}